// round 4
// baseline (speedup 1.0000x reference)
#include <cuda_runtime.h>
#include <math.h>
#include <stdint.h>

#define DIMM   1024
#define DEPTH  4
#define HEADS  16
#define DHEAD  64
#define MLPD   4096
#define INNER  1024
#define BATCH  4
#define SEQ    1024
#define TOK    (BATCH*SEQ)
#define QKV3   (3*INNER)

__device__ float g_x   [TOK*DIMM];
__device__ float g_h   [TOK*DIMM];
__device__ float g_qkv [TOK*QKV3];
__device__ float g_att [TOK*INNER];
__device__ float g_mlp [TOK*MLPD];
// tf32-prerounded weight copies
__device__ float g_wqkv[DEPTH*DIMM*QKV3];
__device__ float g_wout[DEPTH*INNER*DIMM];
__device__ float g_w1  [DEPTH*DIMM*MLPD];
__device__ float g_w2  [DEPTH*MLPD*DIMM];

__device__ __forceinline__ float tfr(float x){
    uint32_t u; asm("cvt.rna.tf32.f32 %0, %1;" : "=r"(u) : "f"(x));
    return __uint_as_float(u);
}
__device__ __forceinline__ uint32_t smem_u32(const void* p){
    return (uint32_t)__cvta_generic_to_shared(p);
}
#define CP16(dst, src) asm volatile("cp.async.cg.shared.global [%0], [%1], 16;\n" :: "r"(dst), "l"(src))
#define CP_COMMIT()    asm volatile("cp.async.commit_group;\n")
#define CP_WAIT1()     asm volatile("cp.async.wait_group 1;\n")

#define MMA_TF32(d, a, b) \
  asm volatile("mma.sync.aligned.m16n8k8.row.col.f32.tf32.tf32.f32 " \
    "{%0,%1,%2,%3},{%4,%5,%6,%7},{%8,%9},{%0,%1,%2,%3};" \
    : "+f"((d)[0]),"+f"((d)[1]),"+f"((d)[2]),"+f"((d)[3]) \
    : "r"((a)[0]),"r"((a)[1]),"r"((a)[2]),"r"((a)[3]),"r"((b)[0]),"r"((b)[1]))

// ---------------- weight pre-rounding --------------------------------------
__global__ void cvt_kernel(const float* __restrict__ s, float* __restrict__ d, int n4)
{
    int i = blockIdx.x * blockDim.x + threadIdx.x;
    if (i < n4){
        float4 v = ((const float4*)s)[i];
        v.x = tfr(v.x); v.y = tfr(v.y); v.z = tfr(v.z); v.w = tfr(v.w);
        ((float4*)d)[i] = v;
    }
}

// ---------------- LayerNorm (output tf32-rounded) ---------------------------
__global__ void ln_kernel(const float* __restrict__ in, float* __restrict__ out,
                          const float* __restrict__ gg, const float* __restrict__ bb)
{
    __shared__ float sh[8], sh2[8];
    int row = blockIdx.x;
    int tid = threadIdx.x;
    const float4 xv = ((const float4*)(in + (size_t)row*DIMM))[tid];
    float s  = xv.x + xv.y + xv.z + xv.w;
    float s2 = xv.x*xv.x + xv.y*xv.y + xv.z*xv.z + xv.w*xv.w;
    #pragma unroll
    for (int o = 16; o > 0; o >>= 1) {
        s  += __shfl_xor_sync(0xffffffffu, s,  o);
        s2 += __shfl_xor_sync(0xffffffffu, s2, o);
    }
    if ((tid & 31) == 0) { sh[tid>>5] = s; sh2[tid>>5] = s2; }
    __syncthreads();
    s  = sh[0]+sh[1]+sh[2]+sh[3]+sh[4]+sh[5]+sh[6]+sh[7];
    s2 = sh2[0]+sh2[1]+sh2[2]+sh2[3]+sh2[4]+sh2[5]+sh2[6]+sh2[7];
    float mean = s * (1.0f/DIMM);
    float var  = s2 * (1.0f/DIMM) - mean*mean;
    float rs   = rsqrtf(var + 1e-5f);
    const float4 gv = ((const float4*)gg)[tid];
    const float4 bv = ((const float4*)bb)[tid];
    float4 ov;
    ov.x = tfr((xv.x - mean)*rs*gv.x + bv.x);
    ov.y = tfr((xv.y - mean)*rs*gv.y + bv.y);
    ov.z = tfr((xv.z - mean)*rs*gv.z + bv.z);
    ov.w = tfr((xv.w - mean)*rs*gv.w + bv.w);
    ((float4*)(out + (size_t)row*DIMM))[tid] = ov;
}

// ---------------- TF32 GEMM with cp.async pipeline ---------------------------
// Inputs must already be tf32-rounded. block 128x128, 8 warps, warp 64x32.
// EPI: 0 plain, 1 +bias+GELU(rounded), 2 +bias+residual
template<int EPI>
__global__ void __launch_bounds__(256, 2)
tgemm(const float* __restrict__ A, const float* __restrict__ B,
      float* __restrict__ C, const float* __restrict__ bias,
      const float* __restrict__ R, int M, int Nn, int K)
{
    __shared__ float As[2][128*20];   // [m][k], stride 20
    __shared__ float Bs[2][16*136];   // [k][n], stride 136
    const int tid  = threadIdx.x;
    const int warp = tid >> 5, lane = tid & 31;
    const int g = lane >> 2, t = lane & 3;
    const int wm = (warp >> 2) * 64;
    const int wn = (warp & 3) * 32;
    const int brow = blockIdx.y * 128;
    const int bcol = blockIdx.x * 128;

    // async-copy assignments: A 128x16 (8 floats/thread), B 16x128 (8 floats/thread)
    const int am  = tid >> 1,  akq = (tid & 1) * 8;
    const int bk  = tid >> 4,  bnq = (tid & 15) * 8;
    const float* Asrc = A + (size_t)(brow + am) * K + akq;
    const float* Bsrc = B + (size_t)bk * Nn + bcol + bnq;

    float acc[4][4][4];
    #pragma unroll
    for (int i = 0; i < 4; i++)
      #pragma unroll
      for (int j = 0; j < 4; j++)
        { acc[i][j][0]=0.f; acc[i][j][1]=0.f; acc[i][j][2]=0.f; acc[i][j][3]=0.f; }

    auto prefetch = [&](int k0, int buf){
        const float* as = Asrc + k0;
        uint32_t ad = smem_u32(&As[buf][am*20 + akq]);
        CP16(ad, as); CP16(ad + 16, as + 4);
        const float* bs = Bsrc + (size_t)k0 * Nn;
        uint32_t bd = smem_u32(&Bs[buf][bk*136 + bnq]);
        CP16(bd, bs); CP16(bd + 16, bs + 4);
    };

    prefetch(0, 0); CP_COMMIT();

    const int nk = K >> 4;
    for (int kk = 0; kk < nk; kk++){
        const int cur = kk & 1;
        if (kk + 1 < nk) prefetch((kk + 1) << 4, cur ^ 1);
        CP_COMMIT();
        CP_WAIT1();
        __syncthreads();

        const float* as = As[cur];
        const float* bs = Bs[cur];
        #pragma unroll
        for (int s = 0; s < 2; s++){
            const int kb = s * 8;
            uint32_t af[4][4], bf[4][2];
            #pragma unroll
            for (int mt = 0; mt < 4; mt++){
                const float* p = as + (wm + mt*16 + g)*20 + kb + t;
                af[mt][0] = __float_as_uint(p[0]);
                af[mt][1] = __float_as_uint(p[8*20]);
                af[mt][2] = __float_as_uint(p[4]);
                af[mt][3] = __float_as_uint(p[8*20 + 4]);
            }
            #pragma unroll
            for (int nt = 0; nt < 4; nt++){
                const float* p = bs + (kb + t)*136 + wn + nt*8 + g;
                bf[nt][0] = __float_as_uint(p[0]);
                bf[nt][1] = __float_as_uint(p[4*136]);
            }
            #pragma unroll
            for (int mt = 0; mt < 4; mt++)
              #pragma unroll
              for (int nt = 0; nt < 4; nt++)
                MMA_TF32(acc[mt][nt], af[mt], bf[nt]);
        }
        __syncthreads();
    }

    #pragma unroll
    for (int mt = 0; mt < 4; mt++){
        const int r0 = brow + wm + mt*16 + g;
        #pragma unroll
        for (int nt = 0; nt < 4; nt++){
            const int c = bcol + wn + nt*8 + 2*t;
            float v[4] = {acc[mt][nt][0], acc[mt][nt][1], acc[mt][nt][2], acc[mt][nt][3]};
            if (EPI >= 1){
                const float b0 = bias[c], b1 = bias[c+1];
                v[0]+=b0; v[1]+=b1; v[2]+=b0; v[3]+=b1;
            }
            if (EPI == 1){
                #pragma unroll
                for (int q = 0; q < 4; q++)
                    v[q] = tfr(0.5f * v[q] * (1.0f + erff(v[q] * 0.70710678118654752f)));
            }
            if (EPI == 2){
                const float2 r0v = *(const float2*)(R + (size_t)r0*Nn + c);
                const float2 r1v = *(const float2*)(R + (size_t)(r0+8)*Nn + c);
                v[0]+=r0v.x; v[1]+=r0v.y; v[2]+=r1v.x; v[3]+=r1v.y;
            }
            float2 o0 = {v[0], v[1]}, o1 = {v[2], v[3]};
            *(float2*)(C + (size_t)r0    *Nn + c) = o0;
            *(float2*)(C + (size_t)(r0+8)*Nn + c) = o1;
        }
    }
}

// ---------------- Fused flash attention (output tf32-rounded) ---------------
__global__ void __launch_bounds__(256, 2)
flash_kernel(const float* __restrict__ qkv, float* __restrict__ att,
             const int* __restrict__ mnp, const int* __restrict__ mbt)
{
    __shared__ float Ks[64*68];
    __shared__ float Vs[64*72];
    __shared__ float cmask[SEQ];

    const int tid = threadIdx.x, warp = tid >> 5, lane = tid & 31;
    const int g = lane >> 2, t = lane & 3;
    const int bh = blockIdx.y, b = bh >> 4, h = bh & 15;
    const int i0 = blockIdx.x * 128;

    const float* qb    = qkv + (size_t)(b*SEQ + i0) * QKV3 + h*DHEAD;
    const float* kbase = qkv + (size_t)(b*SEQ) * QKV3 + INNER   + h*DHEAD;
    const float* vbase = qkv + (size_t)(b*SEQ) * QKV3 + 2*INNER + h*DHEAD;

    {
        const int j = tid * 4;
        const int4 a = *(const int4*)(mnp + b*SEQ + j);
        const int4 c = *(const int4*)(mbt + b*SEQ + j);
        cmask[j+0] = (a.x != 0 && c.x != 1) ? 1.f : 0.f;
        cmask[j+1] = (a.y != 0 && c.y != 1) ? 1.f : 0.f;
        cmask[j+2] = (a.z != 0 && c.z != 1) ? 1.f : 0.f;
        cmask[j+3] = (a.w != 0 && c.w != 1) ? 1.f : 0.f;
    }

    #pragma unroll
    for (int it = 0; it < 8; it++){
        const int idx = tid + it*256;
        const int r = idx >> 4, c4 = (idx & 15) * 4;
        const float4 q = *(const float4*)(qb + (size_t)r*QKV3 + c4);
        float* dst = (r < 64) ? &Ks[r*68 + c4] : &Vs[(r-64)*72 + c4];
        dst[0]=tfr(q.x); dst[1]=tfr(q.y); dst[2]=tfr(q.z); dst[3]=tfr(q.w);
    }
    __syncthreads();

    uint32_t qa[8][4];
    {
        const float* buf = (warp < 4) ? &Ks[(warp*16)*68] : &Vs[((warp-4)*16)*72];
        const int st = (warp < 4) ? 68 : 72;
        #pragma unroll
        for (int kc = 0; kc < 8; kc++){
            const float* p = buf + g*st + kc*8 + t;
            qa[kc][0] = __float_as_uint(p[0]);
            qa[kc][1] = __float_as_uint(p[8*st]);
            qa[kc][2] = __float_as_uint(p[4]);
            qa[kc][3] = __float_as_uint(p[8*st + 4]);
        }
    }

    const int qrow = i0 + warp*16;
    const bool rm0 = (mnp[b*SEQ + qrow + g    ] == 0);
    const bool rm1 = (mnp[b*SEQ + qrow + g + 8] == 0);

    float m0 = -1e30f, m1 = -1e30f, l0 = 0.f, l1 = 0.f;
    float o[8][4];
    #pragma unroll
    for (int nt = 0; nt < 8; nt++){ o[nt][0]=0.f; o[nt][1]=0.f; o[nt][2]=0.f; o[nt][3]=0.f; }

    const int src0 = (lane & ~3) | (t >> 1);
    const int src1 = src0 + 2;

    for (int jt = 0; jt < 16; jt++){
        __syncthreads();
        #pragma unroll
        for (int it = 0; it < 4; it++){
            const int idx = tid + it*256;
            const int r = idx >> 4, c4 = (idx & 15) * 4;
            const size_t gr = (size_t)(jt*64 + r) * QKV3;
            const float4 kv = *(const float4*)(kbase + gr + c4);
            float* dk = &Ks[r*68 + c4];
            dk[0]=tfr(kv.x); dk[1]=tfr(kv.y); dk[2]=tfr(kv.z); dk[3]=tfr(kv.w);
            const float4 vv = *(const float4*)(vbase + gr + c4);
            float* dv = &Vs[r*72 + c4];
            dv[0]=tfr(vv.x); dv[1]=tfr(vv.y); dv[2]=tfr(vv.z); dv[3]=tfr(vv.w);
        }
        __syncthreads();

        float s[8][4];
        #pragma unroll
        for (int nc = 0; nc < 8; nc++){ s[nc][0]=0.f; s[nc][1]=0.f; s[nc][2]=0.f; s[nc][3]=0.f; }
        #pragma unroll
        for (int kc = 0; kc < 8; kc++){
            #pragma unroll
            for (int nc = 0; nc < 8; nc++){
                uint32_t bf[2];
                const float* p = &Ks[(nc*8 + g)*68 + kc*8 + t];
                bf[0] = __float_as_uint(p[0]);
                bf[1] = __float_as_uint(p[4]);
                MMA_TF32(s[nc], qa[kc], bf);
            }
        }

        float mx0 = -1e30f, mx1 = -1e30f;
        #pragma unroll
        for (int nc = 0; nc < 8; nc++){
            const int j = jt*64 + nc*8 + 2*t;
            const float c0v = cmask[j], c1v = cmask[j+1];
            s[nc][0] = (rm0 || c0v == 0.f) ? -1000.f : s[nc][0]*0.125f;
            s[nc][1] = (rm0 || c1v == 0.f) ? -1000.f : s[nc][1]*0.125f;
            s[nc][2] = (rm1 || c0v == 0.f) ? -1000.f : s[nc][2]*0.125f;
            s[nc][3] = (rm1 || c1v == 0.f) ? -1000.f : s[nc][3]*0.125f;
            mx0 = fmaxf(mx0, fmaxf(s[nc][0], s[nc][1]));
            mx1 = fmaxf(mx1, fmaxf(s[nc][2], s[nc][3]));
        }
        mx0 = fmaxf(mx0, __shfl_xor_sync(0xffffffffu, mx0, 1));
        mx0 = fmaxf(mx0, __shfl_xor_sync(0xffffffffu, mx0, 2));
        mx1 = fmaxf(mx1, __shfl_xor_sync(0xffffffffu, mx1, 1));
        mx1 = fmaxf(mx1, __shfl_xor_sync(0xffffffffu, mx1, 2));

        const float nm0 = fmaxf(m0, mx0), nm1 = fmaxf(m1, mx1);
        const float a0 = __expf(m0 - nm0), a1 = __expf(m1 - nm1);

        float r0s = 0.f, r1s = 0.f;
        uint32_t pb[8][4];
        #pragma unroll
        for (int nc = 0; nc < 8; nc++){
            const float e0 = __expf(s[nc][0] - nm0);
            const float e1 = __expf(s[nc][1] - nm0);
            const float e2 = __expf(s[nc][2] - nm1);
            const float e3 = __expf(s[nc][3] - nm1);
            r0s += e0 + e1; r1s += e2 + e3;
            pb[nc][0] = __float_as_uint(tfr(e0));
            pb[nc][1] = __float_as_uint(tfr(e1));
            pb[nc][2] = __float_as_uint(tfr(e2));
            pb[nc][3] = __float_as_uint(tfr(e3));
        }
        r0s += __shfl_xor_sync(0xffffffffu, r0s, 1);
        r0s += __shfl_xor_sync(0xffffffffu, r0s, 2);
        r1s += __shfl_xor_sync(0xffffffffu, r1s, 1);
        r1s += __shfl_xor_sync(0xffffffffu, r1s, 2);

        l0 = l0*a0 + r0s; l1 = l1*a1 + r1s;
        m0 = nm0; m1 = nm1;

        #pragma unroll
        for (int nt = 0; nt < 8; nt++){
            o[nt][0] *= a0; o[nt][1] *= a0;
            o[nt][2] *= a1; o[nt][3] *= a1;
        }

        #pragma unroll
        for (int kc = 0; kc < 8; kc++){
            uint32_t af[4];
            {
                const uint32_t v0 = __shfl_sync(0xffffffffu, pb[kc][0], src0);
                const uint32_t v1 = __shfl_sync(0xffffffffu, pb[kc][1], src0);
                af[0] = (t & 1) ? v1 : v0;
                const uint32_t v2 = __shfl_sync(0xffffffffu, pb[kc][2], src0);
                const uint32_t v3 = __shfl_sync(0xffffffffu, pb[kc][3], src0);
                af[1] = (t & 1) ? v3 : v2;
                const uint32_t w0 = __shfl_sync(0xffffffffu, pb[kc][0], src1);
                const uint32_t w1 = __shfl_sync(0xffffffffu, pb[kc][1], src1);
                af[2] = (t & 1) ? w1 : w0;
                const uint32_t w2 = __shfl_sync(0xffffffffu, pb[kc][2], src1);
                const uint32_t w3 = __shfl_sync(0xffffffffu, pb[kc][3], src1);
                af[3] = (t & 1) ? w3 : w2;
            }
            #pragma unroll
            for (int nt = 0; nt < 8; nt++){
                uint32_t bf[2];
                const float* p = &Vs[(kc*8 + t)*72 + nt*8 + g];
                bf[0] = __float_as_uint(p[0]);
                bf[1] = __float_as_uint(p[4*72]);
                MMA_TF32(o[nt], af, bf);
            }
        }
    }

    const float inv0 = 1.0f / l0, inv1 = 1.0f / l1;
    const size_t r0 = (size_t)(b*SEQ + qrow + g);
    #pragma unroll
    for (int nt = 0; nt < 8; nt++){
        const int c = h*DHEAD + nt*8 + 2*t;
        float2 w0 = {tfr(o[nt][0]*inv0), tfr(o[nt][1]*inv0)};
        float2 w1 = {tfr(o[nt][2]*inv1), tfr(o[nt][3]*inv1)};
        *(float2*)(att + r0      * INNER + c) = w0;
        *(float2*)(att + (r0 + 8) * INNER + c) = w1;
    }
}

// ---------------------------------------------------------------------------
extern "C" void kernel_launch(void* const* d_in, const int* in_sizes, int n_in,
                              void* d_out, int out_size)
{
    const float* x    = (const float*)d_in[0];
    const float* Wqkv = (const float*)d_in[1];
    const float* Wout = (const float*)d_in[2];
    const float* bout = (const float*)d_in[3];
    const float* ln1g = (const float*)d_in[4];
    const float* ln1b = (const float*)d_in[5];
    const float* W1   = (const float*)d_in[6];
    const float* b1   = (const float*)d_in[7];
    const float* W2   = (const float*)d_in[8];
    const float* b2   = (const float*)d_in[9];
    const float* ln2g = (const float*)d_in[10];
    const float* ln2b = (const float*)d_in[11];
    const int*   mnp  = (const int*)d_in[12];
    const int*   mbt  = (const int*)d_in[13];

    float *gx, *gh, *gqkv, *gatt, *gmlp, *wqkv, *wout, *w1, *w2;
    cudaGetSymbolAddress((void**)&gx,   g_x);
    cudaGetSymbolAddress((void**)&gh,   g_h);
    cudaGetSymbolAddress((void**)&gqkv, g_qkv);
    cudaGetSymbolAddress((void**)&gatt, g_att);
    cudaGetSymbolAddress((void**)&gmlp, g_mlp);
    cudaGetSymbolAddress((void**)&wqkv, g_wqkv);
    cudaGetSymbolAddress((void**)&wout, g_wout);
    cudaGetSymbolAddress((void**)&w1,   g_w1);
    cudaGetSymbolAddress((void**)&w2,   g_w2);

    // pre-round weights to tf32 (once per launch)
    {
        int n;
        n = DEPTH*DIMM*QKV3/4;  cvt_kernel<<<(n+255)/256, 256>>>(Wqkv, wqkv, n);
        n = DEPTH*INNER*DIMM/4; cvt_kernel<<<(n+255)/256, 256>>>(Wout, wout, n);
        n = DEPTH*DIMM*MLPD/4;  cvt_kernel<<<(n+255)/256, 256>>>(W1,   w1,   n);
        n = DEPTH*MLPD*DIMM/4;  cvt_kernel<<<(n+255)/256, 256>>>(W2,   w2,   n);
    }

    cudaMemcpyAsync(gx, x, (size_t)TOK * DIMM * sizeof(float),
                    cudaMemcpyDeviceToDevice);

    for (int l = 0; l < DEPTH; l++) {
        ln_kernel<<<TOK, 256>>>(gx, gh, ln1g + l*DIMM, ln1b + l*DIMM);
        tgemm<0><<<dim3(QKV3/128, TOK/128), 256>>>(
            gh, wqkv + (size_t)l*DIMM*QKV3, gqkv, nullptr, nullptr,
            TOK, QKV3, DIMM);
        flash_kernel<<<dim3(SEQ/128, BATCH*HEADS), 256>>>(gqkv, gatt, mnp, mbt);
        tgemm<2><<<dim3(DIMM/128, TOK/128), 256>>>(
            gatt, wout + (size_t)l*INNER*DIMM, gx, bout + l*DIMM, gx,
            TOK, DIMM, INNER);
        ln_kernel<<<TOK, 256>>>(gx, gh, ln2g + l*DIMM, ln2b + l*DIMM);
        tgemm<1><<<dim3(MLPD/128, TOK/128), 256>>>(
            gh, w1 + (size_t)l*DIMM*MLPD, gmlp, b1 + l*MLPD, nullptr,
            TOK, MLPD, DIMM);
        tgemm<2><<<dim3(DIMM/128, TOK/128), 256>>>(
            gmlp, w2 + (size_t)l*MLPD*DIMM, gx, b2 + l*DIMM, gx,
            TOK, DIMM, MLPD);
    }

    cudaMemcpyAsync(d_out, gx, (size_t)TOK * DIMM * sizeof(float),
                    cudaMemcpyDeviceToDevice);
}

// round 6
// speedup vs baseline: 1.2881x; 1.2881x over previous
#include <cuda_runtime.h>
#include <math.h>
#include <stdint.h>

#define DIMM   1024
#define DEPTH  4
#define HEADS  16
#define DHEAD  64
#define MLPD   4096
#define INNER  1024
#define BATCH  4
#define SEQ    1024
#define TOK    (BATCH*SEQ)
#define QKV3   (3*INNER)

// ---------------- scratch ----------------------------------------------------
__device__ float g_x   [TOK*DIMM];
__device__ float g_h   [TOK*DIMM];
__device__ float g_qkv [TOK*QKV3];
__device__ float g_att [TOK*INNER];
__device__ float g_mlp [TOK*MLPD];
// transposed + tf32-rounded weights, per layer stored [N][K]
__device__ float g_wqkv[(size_t)DEPTH*QKV3*DIMM];
__device__ float g_wout[(size_t)DEPTH*DIMM*INNER];
__device__ float g_w1  [(size_t)DEPTH*MLPD*DIMM];
__device__ float g_w2  [(size_t)DEPTH*DIMM*MLPD];

__device__ __forceinline__ float tfr(float x){
    uint32_t u; asm("cvt.rna.tf32.f32 %0, %1;" : "=r"(u) : "f"(x));
    return __uint_as_float(u);
}
__device__ __forceinline__ uint32_t smem_u32(const void* p){
    return (uint32_t)__cvta_generic_to_shared(p);
}
#define CP16(dst, src) asm volatile("cp.async.cg.shared.global [%0], [%1], 16;\n" :: "r"(dst), "l"(src))
#define CP_COMMIT()    asm volatile("cp.async.commit_group;\n" ::: "memory")
#define CP_WAIT1()     asm volatile("cp.async.wait_group 1;\n" ::: "memory")

#define MMA_TF32(d, a, b) \
  asm volatile("mma.sync.aligned.m16n8k8.row.col.f32.tf32.tf32.f32 " \
    "{%0,%1,%2,%3},{%4,%5,%6,%7},{%8,%9},{%0,%1,%2,%3};" \
    : "+f"((d)[0]),"+f"((d)[1]),"+f"((d)[2]),"+f"((d)[3]) \
    : "r"((a)[0]),"r"((a)[1]),"r"((a)[2]),"r"((a)[3]),"r"((b)[0]),"r"((b)[1]))

__device__ __forceinline__ void ldsm_x4(uint32_t* r, uint32_t a){
    asm volatile("ldmatrix.sync.aligned.m8n8.x4.shared.b16 {%0,%1,%2,%3}, [%4];"
        : "=r"(r[0]),"=r"(r[1]),"=r"(r[2]),"=r"(r[3]) : "r"(a));
}
__device__ __forceinline__ void ldsm_x2(uint32_t* r, uint32_t a){
    asm volatile("ldmatrix.sync.aligned.m8n8.x2.shared.b16 {%0,%1}, [%2];"
        : "=r"(r[0]),"=r"(r[1]) : "r"(a));
}

// ---------------- weight transpose + tf32 round ------------------------------
// in: [DEPTH][K][N]  ->  out: [DEPTH][N][K]
__global__ void tr_kernel(const float* __restrict__ in, float* __restrict__ out,
                          int K, int N)
{
    __shared__ float t[32][33];
    const int l = blockIdx.z;
    const float* src = in + (size_t)l*K*N;
    float* dst = out + (size_t)l*K*N;
    const int k0 = blockIdx.y*32, n0 = blockIdx.x*32;
    const int tx = threadIdx.x, ty = threadIdx.y;
    #pragma unroll
    for (int r = ty; r < 32; r += 8)
        t[r][tx] = tfr(src[(size_t)(k0+r)*N + n0+tx]);
    __syncthreads();
    #pragma unroll
    for (int r = ty; r < 32; r += 8)
        dst[(size_t)(n0+r)*K + k0+tx] = t[tx][r];
}

// ---------------- LayerNorm (output tf32-rounded) ----------------------------
__global__ void ln_kernel(const float* __restrict__ in, float* __restrict__ out,
                          const float* __restrict__ gg, const float* __restrict__ bb)
{
    __shared__ float sh[8], sh2[8];
    int row = blockIdx.x;
    int tid = threadIdx.x;
    const float4 xv = ((const float4*)(in + (size_t)row*DIMM))[tid];
    float s  = xv.x + xv.y + xv.z + xv.w;
    float s2 = xv.x*xv.x + xv.y*xv.y + xv.z*xv.z + xv.w*xv.w;
    #pragma unroll
    for (int o = 16; o > 0; o >>= 1) {
        s  += __shfl_xor_sync(0xffffffffu, s,  o);
        s2 += __shfl_xor_sync(0xffffffffu, s2, o);
    }
    if ((tid & 31) == 0) { sh[tid>>5] = s; sh2[tid>>5] = s2; }
    __syncthreads();
    s  = sh[0]+sh[1]+sh[2]+sh[3]+sh[4]+sh[5]+sh[6]+sh[7];
    s2 = sh2[0]+sh2[1]+sh2[2]+sh2[3]+sh2[4]+sh2[5]+sh2[6]+sh2[7];
    float mean = s * (1.0f/DIMM);
    float var  = s2 * (1.0f/DIMM) - mean*mean;
    float rs   = rsqrtf(var + 1e-5f);
    const float4 gv = ((const float4*)gg)[tid];
    const float4 bv = ((const float4*)bb)[tid];
    float4 ov;
    ov.x = tfr((xv.x - mean)*rs*gv.x + bv.x);
    ov.y = tfr((xv.y - mean)*rs*gv.y + bv.y);
    ov.z = tfr((xv.z - mean)*rs*gv.z + bv.z);
    ov.w = tfr((xv.w - mean)*rs*gv.w + bv.w);
    ((float4*)(out + (size_t)row*DIMM))[tid] = ov;
}

// ---------------- TF32 GEMM: ldmatrix fragments + cp.async 3-stage -----------
// C[M,Nn] = A[M,K] @ Bt[Nn,K]^T. A, Bt tf32-prerounded, K-contiguous rows.
// Smem tiles [128 rows][16 k + 4 pad] = 80 B/row. 8 warps, warp tile 64x32.
// EPI: 0 plain, 1 +bias+GELU(rounded), 2 +bias+residual
#define ABYTES (128*20*4)      // 10240
#define STGB   (2*ABYTES)      // 20480
#define NSTG   3
#define SMTOT  (NSTG*STGB)     // 61440

template<int EPI>
__global__ void __launch_bounds__(256, 2)
tgemm(const float* __restrict__ A, const float* __restrict__ Bt,
      float* __restrict__ C, const float* __restrict__ bias,
      const float* __restrict__ R, int M, int Nn, int K)
{
    extern __shared__ float sm[];
    const uint32_t sb = smem_u32(sm);
    const int tid = threadIdx.x, warp = tid >> 5, lane = tid & 31;
    const int g = lane >> 2, t = lane & 3;
    const int wm = (warp >> 2) * 64;
    const int wn = (warp & 3) * 32;
    const int brow = blockIdx.y * 128;
    const int bcol = blockIdx.x * 128;

    float acc[4][4][4];
    #pragma unroll
    for (int i = 0; i < 4; i++)
      #pragma unroll
      for (int j = 0; j < 4; j++)
        { acc[i][j][0]=0.f; acc[i][j][1]=0.f; acc[i][j][2]=0.f; acc[i][j][3]=0.f; }

    // cp.async: 512 16B-chunks per operand tile; thread does 2 A + 2 B
    auto prefetch = [&](int blk){
        const uint32_t ab = sb + (uint32_t)((blk % NSTG) * STGB);
        const uint32_t bb = ab + ABYTES;
        const int kof = blk * 16;
        #pragma unroll
        for (int j = 0; j < 2; j++){
            const int c = tid + j*256;
            const int row = c >> 2, q = c & 3;
            CP16(ab + (uint32_t)(row*80 + q*16), A  + (size_t)(brow+row)*K + kof + q*4);
            CP16(bb + (uint32_t)(row*80 + q*16), Bt + (size_t)(bcol+row)*K + kof + q*4);
        }
    };

    prefetch(0); CP_COMMIT();
    prefetch(1); CP_COMMIT();

    // ldmatrix per-lane address components
    const uint32_t aoff = (uint32_t)((wm + (lane & 15))*80 + (lane >> 4)*16);
    const uint32_t boff = (uint32_t)((wn + (lane & 7))*80 + ((lane >> 3) & 1)*16) + ABYTES;

    const int nk = K >> 4;
    for (int i = 0; i < nk; i++){
        CP_WAIT1();
        __syncthreads();
        const uint32_t stg = sb + (uint32_t)((i % NSTG) * STGB);
        #pragma unroll
        for (int s = 0; s < 2; s++){
            uint32_t af[4][4], bf[4][2];
            #pragma unroll
            for (int mt = 0; mt < 4; mt++)
                ldsm_x4(af[mt], stg + aoff + (uint32_t)(mt*1280 + s*32));
            #pragma unroll
            for (int nt = 0; nt < 4; nt++)
                ldsm_x2(bf[nt], stg + boff + (uint32_t)(nt*640 + s*32));
            #pragma unroll
            for (int mt = 0; mt < 4; mt++)
              #pragma unroll
              for (int nt = 0; nt < 4; nt++)
                MMA_TF32(acc[mt][nt], af[mt], bf[nt]);
        }
        if (i + 2 < nk) prefetch(i + 2);
        CP_COMMIT();
    }

    // epilogue: pairs (c0,c1) at row g, (c2,c3) at row g+8
    #pragma unroll
    for (int mt = 0; mt < 4; mt++){
        const int r0 = brow + wm + mt*16 + g;
        #pragma unroll
        for (int nt = 0; nt < 4; nt++){
            const int c = bcol + wn + nt*8 + 2*t;
            float v[4] = {acc[mt][nt][0], acc[mt][nt][1], acc[mt][nt][2], acc[mt][nt][3]};
            if (EPI >= 1){
                const float b0 = bias[c], b1 = bias[c+1];
                v[0]+=b0; v[1]+=b1; v[2]+=b0; v[3]+=b1;
            }
            if (EPI == 1){
                #pragma unroll
                for (int q = 0; q < 4; q++)
                    v[q] = tfr(0.5f * v[q] * (1.0f + erff(v[q] * 0.70710678118654752f)));
            }
            if (EPI == 2){
                const float2 r0v = *(const float2*)(R + (size_t)r0*Nn + c);
                const float2 r1v = *(const float2*)(R + (size_t)(r0+8)*Nn + c);
                v[0]+=r0v.x; v[1]+=r0v.y; v[2]+=r1v.x; v[3]+=r1v.y;
            }
            float2 o0 = {v[0], v[1]}, o1 = {v[2], v[3]};
            *(float2*)(C + (size_t)r0    *Nn + c) = o0;
            *(float2*)(C + (size_t)(r0+8)*Nn + c) = o1;
        }
    }
}

// ---------------- Fused flash attention (output tf32-rounded) ----------------
__global__ void __launch_bounds__(256, 2)
flash_kernel(const float* __restrict__ qkv, float* __restrict__ att,
             const int* __restrict__ mnp, const int* __restrict__ mbt)
{
    __shared__ float Ks[64*68];
    __shared__ float Vs[64*72];
    __shared__ float cmask[SEQ];

    const int tid = threadIdx.x, warp = tid >> 5, lane = tid & 31;
    const int g = lane >> 2, t = lane & 3;
    const int bh = blockIdx.y, b = bh >> 4, h = bh & 15;
    const int i0 = blockIdx.x * 128;

    const float* qb    = qkv + (size_t)(b*SEQ + i0) * QKV3 + h*DHEAD;
    const float* kbase = qkv + (size_t)(b*SEQ) * QKV3 + INNER   + h*DHEAD;
    const float* vbase = qkv + (size_t)(b*SEQ) * QKV3 + 2*INNER + h*DHEAD;

    {
        const int j = tid * 4;
        const int4 a = *(const int4*)(mnp + b*SEQ + j);
        const int4 c = *(const int4*)(mbt + b*SEQ + j);
        cmask[j+0] = (a.x != 0 && c.x != 1) ? 1.f : 0.f;
        cmask[j+1] = (a.y != 0 && c.y != 1) ? 1.f : 0.f;
        cmask[j+2] = (a.z != 0 && c.z != 1) ? 1.f : 0.f;
        cmask[j+3] = (a.w != 0 && c.w != 1) ? 1.f : 0.f;
    }

    #pragma unroll
    for (int it = 0; it < 8; it++){
        const int idx = tid + it*256;
        const int r = idx >> 4, c4 = (idx & 15) * 4;
        const float4 q = *(const float4*)(qb + (size_t)r*QKV3 + c4);
        float* dst = (r < 64) ? &Ks[r*68 + c4] : &Vs[(r-64)*72 + c4];
        dst[0]=tfr(q.x); dst[1]=tfr(q.y); dst[2]=tfr(q.z); dst[3]=tfr(q.w);
    }
    __syncthreads();

    uint32_t qa[8][4];
    {
        const float* buf = (warp < 4) ? &Ks[(warp*16)*68] : &Vs[((warp-4)*16)*72];
        const int st = (warp < 4) ? 68 : 72;
        #pragma unroll
        for (int kc = 0; kc < 8; kc++){
            const float* p = buf + g*st + kc*8 + t;
            qa[kc][0] = __float_as_uint(p[0]);
            qa[kc][1] = __float_as_uint(p[8*st]);
            qa[kc][2] = __float_as_uint(p[4]);
            qa[kc][3] = __float_as_uint(p[8*st + 4]);
        }
    }

    const int qrow = i0 + warp*16;
    const bool rm0 = (mnp[b*SEQ + qrow + g    ] == 0);
    const bool rm1 = (mnp[b*SEQ + qrow + g + 8] == 0);

    float m0 = -1e30f, m1 = -1e30f, l0 = 0.f, l1 = 0.f;
    float o[8][4];
    #pragma unroll
    for (int nt = 0; nt < 8; nt++){ o[nt][0]=0.f; o[nt][1]=0.f; o[nt][2]=0.f; o[nt][3]=0.f; }

    const int src0 = (lane & ~3) | (t >> 1);
    const int src1 = src0 + 2;

    for (int jt = 0; jt < 16; jt++){
        __syncthreads();
        #pragma unroll
        for (int it = 0; it < 4; it++){
            const int idx = tid + it*256;
            const int r = idx >> 4, c4 = (idx & 15) * 4;
            const size_t gr = (size_t)(jt*64 + r) * QKV3;
            const float4 kv = *(const float4*)(kbase + gr + c4);
            float* dk = &Ks[r*68 + c4];
            dk[0]=tfr(kv.x); dk[1]=tfr(kv.y); dk[2]=tfr(kv.z); dk[3]=tfr(kv.w);
            const float4 vv = *(const float4*)(vbase + gr + c4);
            float* dv = &Vs[r*72 + c4];
            dv[0]=tfr(vv.x); dv[1]=tfr(vv.y); dv[2]=tfr(vv.z); dv[3]=tfr(vv.w);
        }
        __syncthreads();

        float s[8][4];
        #pragma unroll
        for (int nc = 0; nc < 8; nc++){ s[nc][0]=0.f; s[nc][1]=0.f; s[nc][2]=0.f; s[nc][3]=0.f; }
        #pragma unroll
        for (int kc = 0; kc < 8; kc++){
            #pragma unroll
            for (int nc = 0; nc < 8; nc++){
                uint32_t bf[2];
                const float* p = &Ks[(nc*8 + g)*68 + kc*8 + t];
                bf[0] = __float_as_uint(p[0]);
                bf[1] = __float_as_uint(p[4]);
                MMA_TF32(s[nc], qa[kc], bf);
            }
        }

        float mx0 = -1e30f, mx1 = -1e30f;
        #pragma unroll
        for (int nc = 0; nc < 8; nc++){
            const int j = jt*64 + nc*8 + 2*t;
            const float c0v = cmask[j], c1v = cmask[j+1];
            s[nc][0] = (rm0 || c0v == 0.f) ? -1000.f : s[nc][0]*0.125f;
            s[nc][1] = (rm0 || c1v == 0.f) ? -1000.f : s[nc][1]*0.125f;
            s[nc][2] = (rm1 || c0v == 0.f) ? -1000.f : s[nc][2]*0.125f;
            s[nc][3] = (rm1 || c1v == 0.f) ? -1000.f : s[nc][3]*0.125f;
            mx0 = fmaxf(mx0, fmaxf(s[nc][0], s[nc][1]));
            mx1 = fmaxf(mx1, fmaxf(s[nc][2], s[nc][3]));
        }
        mx0 = fmaxf(mx0, __shfl_xor_sync(0xffffffffu, mx0, 1));
        mx0 = fmaxf(mx0, __shfl_xor_sync(0xffffffffu, mx0, 2));
        mx1 = fmaxf(mx1, __shfl_xor_sync(0xffffffffu, mx1, 1));
        mx1 = fmaxf(mx1, __shfl_xor_sync(0xffffffffu, mx1, 2));

        const float nm0 = fmaxf(m0, mx0), nm1 = fmaxf(m1, mx1);
        const float a0 = __expf(m0 - nm0), a1 = __expf(m1 - nm1);

        float r0s = 0.f, r1s = 0.f;
        uint32_t pb[8][4];
        #pragma unroll
        for (int nc = 0; nc < 8; nc++){
            const float e0 = __expf(s[nc][0] - nm0);
            const float e1 = __expf(s[nc][1] - nm0);
            const float e2 = __expf(s[nc][2] - nm1);
            const float e3 = __expf(s[nc][3] - nm1);
            r0s += e0 + e1; r1s += e2 + e3;
            pb[nc][0] = __float_as_uint(tfr(e0));
            pb[nc][1] = __float_as_uint(tfr(e1));
            pb[nc][2] = __float_as_uint(tfr(e2));
            pb[nc][3] = __float_as_uint(tfr(e3));
        }
        r0s += __shfl_xor_sync(0xffffffffu, r0s, 1);
        r0s += __shfl_xor_sync(0xffffffffu, r0s, 2);
        r1s += __shfl_xor_sync(0xffffffffu, r1s, 1);
        r1s += __shfl_xor_sync(0xffffffffu, r1s, 2);

        l0 = l0*a0 + r0s; l1 = l1*a1 + r1s;
        m0 = nm0; m1 = nm1;

        #pragma unroll
        for (int nt = 0; nt < 8; nt++){
            o[nt][0] *= a0; o[nt][1] *= a0;
            o[nt][2] *= a1; o[nt][3] *= a1;
        }

        #pragma unroll
        for (int kc = 0; kc < 8; kc++){
            uint32_t af[4];
            {
                const uint32_t v0 = __shfl_sync(0xffffffffu, pb[kc][0], src0);
                const uint32_t v1 = __shfl_sync(0xffffffffu, pb[kc][1], src0);
                af[0] = (t & 1) ? v1 : v0;
                const uint32_t v2 = __shfl_sync(0xffffffffu, pb[kc][2], src0);
                const uint32_t v3 = __shfl_sync(0xffffffffu, pb[kc][3], src0);
                af[1] = (t & 1) ? v3 : v2;
                const uint32_t w0 = __shfl_sync(0xffffffffu, pb[kc][0], src1);
                const uint32_t w1 = __shfl_sync(0xffffffffu, pb[kc][1], src1);
                af[2] = (t & 1) ? w1 : w0;
                const uint32_t w2 = __shfl_sync(0xffffffffu, pb[kc][2], src1);
                const uint32_t w3 = __shfl_sync(0xffffffffu, pb[kc][3], src1);
                af[3] = (t & 1) ? w3 : w2;
            }
            #pragma unroll
            for (int nt = 0; nt < 8; nt++){
                uint32_t bf[2];
                const float* p = &Vs[(kc*8 + t)*72 + nt*8 + g];
                bf[0] = __float_as_uint(p[0]);
                bf[1] = __float_as_uint(p[4*72]);
                MMA_TF32(o[nt], af, bf);
            }
        }
    }

    const float inv0 = 1.0f / l0, inv1 = 1.0f / l1;
    const size_t r0 = (size_t)(b*SEQ + qrow + g);
    #pragma unroll
    for (int nt = 0; nt < 8; nt++){
        const int c = h*DHEAD + nt*8 + 2*t;
        float2 w0 = {tfr(o[nt][0]*inv0), tfr(o[nt][1]*inv0)};
        float2 w1 = {tfr(o[nt][2]*inv1), tfr(o[nt][3]*inv1)};
        *(float2*)(att + r0      * INNER + c) = w0;
        *(float2*)(att + (r0 + 8) * INNER + c) = w1;
    }
}

// ---------------------------------------------------------------------------
extern "C" void kernel_launch(void* const* d_in, const int* in_sizes, int n_in,
                              void* d_out, int out_size)
{
    const float* x    = (const float*)d_in[0];
    const float* Wqkv = (const float*)d_in[1];
    const float* Wout = (const float*)d_in[2];
    const float* bout = (const float*)d_in[3];
    const float* ln1g = (const float*)d_in[4];
    const float* ln1b = (const float*)d_in[5];
    const float* W1   = (const float*)d_in[6];
    const float* b1   = (const float*)d_in[7];
    const float* W2   = (const float*)d_in[8];
    const float* b2   = (const float*)d_in[9];
    const float* ln2g = (const float*)d_in[10];
    const float* ln2b = (const float*)d_in[11];
    const int*   mnp  = (const int*)d_in[12];
    const int*   mbt  = (const int*)d_in[13];

    float *gx, *gh, *gqkv, *gatt, *gmlp, *wqkv, *wout, *w1, *w2;
    cudaGetSymbolAddress((void**)&gx,   g_x);
    cudaGetSymbolAddress((void**)&gh,   g_h);
    cudaGetSymbolAddress((void**)&gqkv, g_qkv);
    cudaGetSymbolAddress((void**)&gatt, g_att);
    cudaGetSymbolAddress((void**)&gmlp, g_mlp);
    cudaGetSymbolAddress((void**)&wqkv, g_wqkv);
    cudaGetSymbolAddress((void**)&wout, g_wout);
    cudaGetSymbolAddress((void**)&w1,   g_w1);
    cudaGetSymbolAddress((void**)&w2,   g_w2);

    cudaFuncSetAttribute(tgemm<0>, cudaFuncAttributeMaxDynamicSharedMemorySize, SMTOT);
    cudaFuncSetAttribute(tgemm<1>, cudaFuncAttributeMaxDynamicSharedMemorySize, SMTOT);
    cudaFuncSetAttribute(tgemm<2>, cudaFuncAttributeMaxDynamicSharedMemorySize, SMTOT);

    // transpose + round weights:  [K][N] -> [N][K]
    tr_kernel<<<dim3(QKV3/32, DIMM/32, DEPTH), dim3(32,8)>>>(Wqkv, wqkv, DIMM, QKV3);
    tr_kernel<<<dim3(DIMM/32, INNER/32, DEPTH), dim3(32,8)>>>(Wout, wout, INNER, DIMM);
    tr_kernel<<<dim3(MLPD/32, DIMM/32, DEPTH), dim3(32,8)>>>(W1,   w1,   DIMM, MLPD);
    tr_kernel<<<dim3(DIMM/32, MLPD/32, DEPTH), dim3(32,8)>>>(W2,   w2,   MLPD, DIMM);

    cudaMemcpyAsync(gx, x, (size_t)TOK * DIMM * sizeof(float),
                    cudaMemcpyDeviceToDevice);

    for (int l = 0; l < DEPTH; l++) {
        ln_kernel<<<TOK, 256>>>(gx, gh, ln1g + l*DIMM, ln1b + l*DIMM);
        tgemm<0><<<dim3(QKV3/128, TOK/128), 256, SMTOT>>>(
            gh, wqkv + (size_t)l*QKV3*DIMM, gqkv, nullptr, nullptr,
            TOK, QKV3, DIMM);
        flash_kernel<<<dim3(SEQ/128, BATCH*HEADS), 256>>>(gqkv, gatt, mnp, mbt);
        tgemm<2><<<dim3(DIMM/128, TOK/128), 256, SMTOT>>>(
            gatt, wout + (size_t)l*DIMM*INNER, gx, bout + l*DIMM, gx,
            TOK, DIMM, INNER);
        ln_kernel<<<TOK, 256>>>(gx, gh, ln2g + l*DIMM, ln2b + l*DIMM);
        tgemm<1><<<dim3(MLPD/128, TOK/128), 256, SMTOT>>>(
            gh, w1 + (size_t)l*MLPD*DIMM, gmlp, b1 + l*MLPD, nullptr,
            TOK, MLPD, DIMM);
        tgemm<2><<<dim3(DIMM/128, TOK/128), 256, SMTOT>>>(
            gmlp, w2 + (size_t)l*DIMM*MLPD, gx, b2 + l*DIMM, gx,
            TOK, DIMM, MLPD);
    }

    cudaMemcpyAsync(d_out, gx, (size_t)TOK * DIMM * sizeof(float),
                    cudaMemcpyDeviceToDevice);
}

// round 7
// speedup vs baseline: 1.3470x; 1.0457x over previous
#include <cuda_runtime.h>
#include <math.h>
#include <stdint.h>

#define DIMM   1024
#define DEPTH  4
#define HEADS  16
#define DHEAD  64
#define MLPD   4096
#define INNER  1024
#define BATCH  4
#define SEQ    1024
#define TOK    (BATCH*SEQ)
#define QKV3   (3*INNER)

// ---------------- scratch ----------------------------------------------------
__device__ float g_x   [TOK*DIMM];
__device__ float g_h   [TOK*DIMM];
__device__ float g_qkv [TOK*QKV3];
__device__ float g_att [TOK*INNER];
__device__ float g_mlp [TOK*MLPD];
// transposed + tf32-rounded weights, per layer stored [N][K]
__device__ float g_wqkv[(size_t)DEPTH*QKV3*DIMM];
__device__ float g_wout[(size_t)DEPTH*DIMM*INNER];
__device__ float g_w1  [(size_t)DEPTH*MLPD*DIMM];
__device__ float g_w2  [(size_t)DEPTH*DIMM*MLPD];

__device__ __forceinline__ float tfr(float x){
    uint32_t u; asm("cvt.rna.tf32.f32 %0, %1;" : "=r"(u) : "f"(x));
    return __uint_as_float(u);
}
__device__ __forceinline__ uint32_t smem_u32(const void* p){
    return (uint32_t)__cvta_generic_to_shared(p);
}
#define CP16(dst, src) asm volatile("cp.async.cg.shared.global [%0], [%1], 16;\n" :: "r"(dst), "l"(src))
#define CP_COMMIT()    asm volatile("cp.async.commit_group;\n" ::: "memory")
#define CP_WAIT1()     asm volatile("cp.async.wait_group 1;\n" ::: "memory")
#define CP_WAIT0()     asm volatile("cp.async.wait_group 0;\n" ::: "memory")

#define MMA_TF32(d, a, b) \
  asm volatile("mma.sync.aligned.m16n8k8.row.col.f32.tf32.tf32.f32 " \
    "{%0,%1,%2,%3},{%4,%5,%6,%7},{%8,%9},{%0,%1,%2,%3};" \
    : "+f"((d)[0]),"+f"((d)[1]),"+f"((d)[2]),"+f"((d)[3]) \
    : "r"((a)[0]),"r"((a)[1]),"r"((a)[2]),"r"((a)[3]),"r"((b)[0]),"r"((b)[1]))

__device__ __forceinline__ void ldsm_x4(uint32_t* r, uint32_t a){
    asm volatile("ldmatrix.sync.aligned.m8n8.x4.shared.b16 {%0,%1,%2,%3}, [%4];"
        : "=r"(r[0]),"=r"(r[1]),"=r"(r[2]),"=r"(r[3]) : "r"(a));
}
__device__ __forceinline__ void ldsm_x2(uint32_t* r, uint32_t a){
    asm volatile("ldmatrix.sync.aligned.m8n8.x2.shared.b16 {%0,%1}, [%2];"
        : "=r"(r[0]),"=r"(r[1]) : "r"(a));
}

// ---------------- weight transpose + tf32 round ------------------------------
__global__ void tr_kernel(const float* __restrict__ in, float* __restrict__ out,
                          int K, int N)
{
    __shared__ float t[32][33];
    const int l = blockIdx.z;
    const float* src = in + (size_t)l*K*N;
    float* dst = out + (size_t)l*K*N;
    const int k0 = blockIdx.y*32, n0 = blockIdx.x*32;
    const int tx = threadIdx.x, ty = threadIdx.y;
    #pragma unroll
    for (int r = ty; r < 32; r += 8)
        t[r][tx] = tfr(src[(size_t)(k0+r)*N + n0+tx]);
    __syncthreads();
    #pragma unroll
    for (int r = ty; r < 32; r += 8)
        dst[(size_t)(n0+r)*K + k0+tx] = t[tx][r];
}

// ---------------- LayerNorm (output tf32-rounded) ----------------------------
__global__ void ln_kernel(const float* __restrict__ in, float* __restrict__ out,
                          const float* __restrict__ gg, const float* __restrict__ bb)
{
    __shared__ float sh[8], sh2[8];
    int row = blockIdx.x;
    int tid = threadIdx.x;
    const float4 xv = ((const float4*)(in + (size_t)row*DIMM))[tid];
    float s  = xv.x + xv.y + xv.z + xv.w;
    float s2 = xv.x*xv.x + xv.y*xv.y + xv.z*xv.z + xv.w*xv.w;
    #pragma unroll
    for (int o = 16; o > 0; o >>= 1) {
        s  += __shfl_xor_sync(0xffffffffu, s,  o);
        s2 += __shfl_xor_sync(0xffffffffu, s2, o);
    }
    if ((tid & 31) == 0) { sh[tid>>5] = s; sh2[tid>>5] = s2; }
    __syncthreads();
    s  = sh[0]+sh[1]+sh[2]+sh[3]+sh[4]+sh[5]+sh[6]+sh[7];
    s2 = sh2[0]+sh2[1]+sh2[2]+sh2[3]+sh2[4]+sh2[5]+sh2[6]+sh2[7];
    float mean = s * (1.0f/DIMM);
    float var  = s2 * (1.0f/DIMM) - mean*mean;
    float rs   = rsqrtf(var + 1e-5f);
    const float4 gv = ((const float4*)gg)[tid];
    const float4 bv = ((const float4*)bb)[tid];
    float4 ov;
    ov.x = tfr((xv.x - mean)*rs*gv.x + bv.x);
    ov.y = tfr((xv.y - mean)*rs*gv.y + bv.y);
    ov.z = tfr((xv.z - mean)*rs*gv.z + bv.z);
    ov.w = tfr((xv.w - mean)*rs*gv.w + bv.w);
    ((float4*)(out + (size_t)row*DIMM))[tid] = ov;
}

// ---------------- TF32 GEMM: BK=32, 3-stage cp.async, ldmatrix ---------------
// C[M,Nn] = A[M,K] @ Bt[Nn,K]^T. A, Bt tf32-prerounded, K-contiguous rows.
// Smem tiles [128 rows][32 k + 4 pad] = 144 B/row. 8 warps, warp tile 64x32.
// EPI: 0 plain, 1 +bias+GELU(round), 2 +bias+residual, 3 plain+round
#define ABY2  (128*36*4)       // 18432
#define STG2  (2*ABY2)         // 36864
#define NSTG  3
#define SMTOT (NSTG*STG2)      // 110592

template<int EPI>
__global__ void __launch_bounds__(256, 2)
tgemm(const float* __restrict__ A, const float* __restrict__ Bt,
      float* __restrict__ C, const float* __restrict__ bias,
      const float* __restrict__ R, int M, int Nn, int K)
{
    extern __shared__ float sm[];
    const uint32_t sb = smem_u32(sm);
    const int tid = threadIdx.x, warp = tid >> 5, lane = tid & 31;
    const int g = lane >> 2, t = lane & 3;
    const int wm = (warp >> 2) * 64;
    const int wn = (warp & 3) * 32;
    const int brow = blockIdx.y * 128;
    const int bcol = blockIdx.x * 128;

    float acc[4][4][4];
    #pragma unroll
    for (int i = 0; i < 4; i++)
      #pragma unroll
      for (int j = 0; j < 4; j++)
        { acc[i][j][0]=0.f; acc[i][j][1]=0.f; acc[i][j][2]=0.f; acc[i][j][3]=0.f; }

    // 128x32 f32 tile = 1024 16B-chunks per operand; 4 A + 4 B chunks/thread
    auto prefetch = [&](int blk){
        const uint32_t ab = sb + (uint32_t)((blk % NSTG) * STG2);
        const uint32_t bb = ab + ABY2;
        const int kof = blk * 32;
        #pragma unroll
        for (int j = 0; j < 4; j++){
            const int c = tid + j*256;
            const int row = c >> 3, q = c & 7;
            CP16(ab + (uint32_t)(row*144 + q*16), A  + (size_t)(brow+row)*K + kof + q*4);
            CP16(bb + (uint32_t)(row*144 + q*16), Bt + (size_t)(bcol+row)*K + kof + q*4);
        }
    };

    prefetch(0); CP_COMMIT();
    prefetch(1); CP_COMMIT();

    const uint32_t aoff = (uint32_t)((wm + (lane & 15))*144 + (lane >> 4)*16);
    const uint32_t boff = (uint32_t)((wn + (lane & 7))*144 + ((lane >> 3) & 1)*16) + ABY2;

    const int nk = K >> 5;
    for (int i = 0; i < nk; i++){
        CP_WAIT1();
        __syncthreads();
        const uint32_t stg = sb + (uint32_t)((i % NSTG) * STG2);
        #pragma unroll
        for (int s = 0; s < 4; s++){
            uint32_t af[4][4], bf[4][2];
            #pragma unroll
            for (int mt = 0; mt < 4; mt++)
                ldsm_x4(af[mt], stg + aoff + (uint32_t)(mt*2304 + s*32));
            #pragma unroll
            for (int nt = 0; nt < 4; nt++)
                ldsm_x2(bf[nt], stg + boff + (uint32_t)(nt*1152 + s*32));
            #pragma unroll
            for (int mt = 0; mt < 4; mt++)
              #pragma unroll
              for (int nt = 0; nt < 4; nt++)
                MMA_TF32(acc[mt][nt], af[mt], bf[nt]);
        }
        if (i + 2 < nk) prefetch(i + 2);
        CP_COMMIT();
    }

    #pragma unroll
    for (int mt = 0; mt < 4; mt++){
        const int r0 = brow + wm + mt*16 + g;
        #pragma unroll
        for (int nt = 0; nt < 4; nt++){
            const int c = bcol + wn + nt*8 + 2*t;
            float v[4] = {acc[mt][nt][0], acc[mt][nt][1], acc[mt][nt][2], acc[mt][nt][3]};
            if (EPI == 1 || EPI == 2){
                const float b0 = bias[c], b1 = bias[c+1];
                v[0]+=b0; v[1]+=b1; v[2]+=b0; v[3]+=b1;
            }
            if (EPI == 1){
                #pragma unroll
                for (int q = 0; q < 4; q++)
                    v[q] = tfr(0.5f * v[q] * (1.0f + erff(v[q] * 0.70710678118654752f)));
            }
            if (EPI == 2){
                const float2 r0v = *(const float2*)(R + (size_t)r0*Nn + c);
                const float2 r1v = *(const float2*)(R + (size_t)(r0+8)*Nn + c);
                v[0]+=r0v.x; v[1]+=r0v.y; v[2]+=r1v.x; v[3]+=r1v.y;
            }
            if (EPI == 3){
                #pragma unroll
                for (int q = 0; q < 4; q++) v[q] = tfr(v[q]);
            }
            float2 o0 = {v[0], v[1]}, o1 = {v[2], v[3]};
            *(float2*)(C + (size_t)r0    *Nn + c) = o0;
            *(float2*)(C + (size_t)(r0+8)*Nn + c) = o1;
        }
    }
}

// ---------------- Fused flash attention (qkv pre-rounded; cp.async staging) --
__global__ void __launch_bounds__(256, 2)
flash_kernel(const float* __restrict__ qkv, float* __restrict__ att,
             const int* __restrict__ mnp, const int* __restrict__ mbt)
{
    __shared__ float Ks[64*68];
    __shared__ float Vs[64*72];
    __shared__ float cmask[SEQ];

    const int tid = threadIdx.x, warp = tid >> 5, lane = tid & 31;
    const int g = lane >> 2, t = lane & 3;
    const int bh = blockIdx.y, b = bh >> 4, h = bh & 15;
    const int i0 = blockIdx.x * 128;

    const float* qb    = qkv + (size_t)(b*SEQ + i0) * QKV3 + h*DHEAD;
    const float* kbase = qkv + (size_t)(b*SEQ) * QKV3 + INNER   + h*DHEAD;
    const float* vbase = qkv + (size_t)(b*SEQ) * QKV3 + 2*INNER + h*DHEAD;

    const uint32_t ks_b = smem_u32(Ks);
    const uint32_t vs_b = smem_u32(Vs);

    {
        const int j = tid * 4;
        const int4 a = *(const int4*)(mnp + b*SEQ + j);
        const int4 c = *(const int4*)(mbt + b*SEQ + j);
        cmask[j+0] = (a.x != 0 && c.x != 1) ? 1.f : 0.f;
        cmask[j+1] = (a.y != 0 && c.y != 1) ? 1.f : 0.f;
        cmask[j+2] = (a.z != 0 && c.z != 1) ? 1.f : 0.f;
        cmask[j+3] = (a.w != 0 && c.w != 1) ? 1.f : 0.f;
    }

    // stage Q (128x64, pre-rounded) into Ks/Vs via cp.async
    #pragma unroll
    for (int it = 0; it < 8; it++){
        const int idx = tid + it*256;
        const int r = idx >> 4, c16 = (idx & 15) * 16;
        const uint32_t dst = (r < 64) ? (ks_b + (uint32_t)(r*272 + c16))
                                      : (vs_b + (uint32_t)((r-64)*288 + c16));
        CP16(dst, qb + (size_t)r*QKV3 + (c16 >> 2));
    }
    CP_COMMIT(); CP_WAIT0();
    __syncthreads();

    uint32_t qa[8][4];
    {
        const float* buf = (warp < 4) ? &Ks[(warp*16)*68] : &Vs[((warp-4)*16)*72];
        const int st = (warp < 4) ? 68 : 72;
        #pragma unroll
        for (int kc = 0; kc < 8; kc++){
            const float* p = buf + g*st + kc*8 + t;
            qa[kc][0] = __float_as_uint(p[0]);
            qa[kc][1] = __float_as_uint(p[8*st]);
            qa[kc][2] = __float_as_uint(p[4]);
            qa[kc][3] = __float_as_uint(p[8*st + 4]);
        }
    }

    const int qrow = i0 + warp*16;
    const bool rm0 = (mnp[b*SEQ + qrow + g    ] == 0);
    const bool rm1 = (mnp[b*SEQ + qrow + g + 8] == 0);

    float m0 = -1e30f, m1 = -1e30f, l0 = 0.f, l1 = 0.f;
    float o[8][4];
    #pragma unroll
    for (int nt = 0; nt < 8; nt++){ o[nt][0]=0.f; o[nt][1]=0.f; o[nt][2]=0.f; o[nt][3]=0.f; }

    const int src0 = (lane & ~3) | (t >> 1);
    const int src1 = src0 + 2;

    for (int jt = 0; jt < 16; jt++){
        __syncthreads();
        #pragma unroll
        for (int it = 0; it < 4; it++){
            const int idx = tid + it*256;
            const int r = idx >> 4, c16 = (idx & 15) * 16;
            const size_t gr = (size_t)(jt*64 + r) * QKV3 + (c16 >> 2);
            CP16(ks_b + (uint32_t)(r*272 + c16), kbase + gr);
            CP16(vs_b + (uint32_t)(r*288 + c16), vbase + gr);
        }
        CP_COMMIT(); CP_WAIT0();
        __syncthreads();

        float s[8][4];
        #pragma unroll
        for (int nc = 0; nc < 8; nc++){ s[nc][0]=0.f; s[nc][1]=0.f; s[nc][2]=0.f; s[nc][3]=0.f; }
        #pragma unroll
        for (int kc = 0; kc < 8; kc++){
            #pragma unroll
            for (int nc = 0; nc < 8; nc++){
                uint32_t bf[2];
                const float* p = &Ks[(nc*8 + g)*68 + kc*8 + t];
                bf[0] = __float_as_uint(p[0]);
                bf[1] = __float_as_uint(p[4]);
                MMA_TF32(s[nc], qa[kc], bf);
            }
        }

        float mx0 = -1e30f, mx1 = -1e30f;
        #pragma unroll
        for (int nc = 0; nc < 8; nc++){
            const int j = jt*64 + nc*8 + 2*t;
            const float c0v = cmask[j], c1v = cmask[j+1];
            s[nc][0] = (rm0 || c0v == 0.f) ? -1000.f : s[nc][0]*0.125f;
            s[nc][1] = (rm0 || c1v == 0.f) ? -1000.f : s[nc][1]*0.125f;
            s[nc][2] = (rm1 || c0v == 0.f) ? -1000.f : s[nc][2]*0.125f;
            s[nc][3] = (rm1 || c1v == 0.f) ? -1000.f : s[nc][3]*0.125f;
            mx0 = fmaxf(mx0, fmaxf(s[nc][0], s[nc][1]));
            mx1 = fmaxf(mx1, fmaxf(s[nc][2], s[nc][3]));
        }
        mx0 = fmaxf(mx0, __shfl_xor_sync(0xffffffffu, mx0, 1));
        mx0 = fmaxf(mx0, __shfl_xor_sync(0xffffffffu, mx0, 2));
        mx1 = fmaxf(mx1, __shfl_xor_sync(0xffffffffu, mx1, 1));
        mx1 = fmaxf(mx1, __shfl_xor_sync(0xffffffffu, mx1, 2));

        const float nm0 = fmaxf(m0, mx0), nm1 = fmaxf(m1, mx1);
        const float a0 = __expf(m0 - nm0), a1 = __expf(m1 - nm1);

        float r0s = 0.f, r1s = 0.f;
        uint32_t pb[8][4];
        #pragma unroll
        for (int nc = 0; nc < 8; nc++){
            const float e0 = __expf(s[nc][0] - nm0);
            const float e1 = __expf(s[nc][1] - nm0);
            const float e2 = __expf(s[nc][2] - nm1);
            const float e3 = __expf(s[nc][3] - nm1);
            r0s += e0 + e1; r1s += e2 + e3;
            pb[nc][0] = __float_as_uint(tfr(e0));
            pb[nc][1] = __float_as_uint(tfr(e1));
            pb[nc][2] = __float_as_uint(tfr(e2));
            pb[nc][3] = __float_as_uint(tfr(e3));
        }
        r0s += __shfl_xor_sync(0xffffffffu, r0s, 1);
        r0s += __shfl_xor_sync(0xffffffffu, r0s, 2);
        r1s += __shfl_xor_sync(0xffffffffu, r1s, 1);
        r1s += __shfl_xor_sync(0xffffffffu, r1s, 2);

        l0 = l0*a0 + r0s; l1 = l1*a1 + r1s;
        m0 = nm0; m1 = nm1;

        #pragma unroll
        for (int nt = 0; nt < 8; nt++){
            o[nt][0] *= a0; o[nt][1] *= a0;
            o[nt][2] *= a1; o[nt][3] *= a1;
        }

        #pragma unroll
        for (int kc = 0; kc < 8; kc++){
            uint32_t af[4];
            {
                const uint32_t v0 = __shfl_sync(0xffffffffu, pb[kc][0], src0);
                const uint32_t v1 = __shfl_sync(0xffffffffu, pb[kc][1], src0);
                af[0] = (t & 1) ? v1 : v0;
                const uint32_t v2 = __shfl_sync(0xffffffffu, pb[kc][2], src0);
                const uint32_t v3 = __shfl_sync(0xffffffffu, pb[kc][3], src0);
                af[1] = (t & 1) ? v3 : v2;
                const uint32_t w0 = __shfl_sync(0xffffffffu, pb[kc][0], src1);
                const uint32_t w1 = __shfl_sync(0xffffffffu, pb[kc][1], src1);
                af[2] = (t & 1) ? w1 : w0;
                const uint32_t w2 = __shfl_sync(0xffffffffu, pb[kc][2], src1);
                const uint32_t w3 = __shfl_sync(0xffffffffu, pb[kc][3], src1);
                af[3] = (t & 1) ? w3 : w2;
            }
            #pragma unroll
            for (int nt = 0; nt < 8; nt++){
                uint32_t bf[2];
                const float* p = &Vs[(kc*8 + t)*72 + nt*8 + g];
                bf[0] = __float_as_uint(p[0]);
                bf[1] = __float_as_uint(p[4*72]);
                MMA_TF32(o[nt], af, bf);
            }
        }
    }

    const float inv0 = 1.0f / l0, inv1 = 1.0f / l1;
    const size_t r0 = (size_t)(b*SEQ + qrow + g);
    #pragma unroll
    for (int nt = 0; nt < 8; nt++){
        const int c = h*DHEAD + nt*8 + 2*t;
        float2 w0 = {tfr(o[nt][0]*inv0), tfr(o[nt][1]*inv0)};
        float2 w1 = {tfr(o[nt][2]*inv1), tfr(o[nt][3]*inv1)};
        *(float2*)(att + r0      * INNER + c) = w0;
        *(float2*)(att + (r0 + 8) * INNER + c) = w1;
    }
}

// ---------------------------------------------------------------------------
extern "C" void kernel_launch(void* const* d_in, const int* in_sizes, int n_in,
                              void* d_out, int out_size)
{
    const float* x    = (const float*)d_in[0];
    const float* Wqkv = (const float*)d_in[1];
    const float* Wout = (const float*)d_in[2];
    const float* bout = (const float*)d_in[3];
    const float* ln1g = (const float*)d_in[4];
    const float* ln1b = (const float*)d_in[5];
    const float* W1   = (const float*)d_in[6];
    const float* b1   = (const float*)d_in[7];
    const float* W2   = (const float*)d_in[8];
    const float* b2   = (const float*)d_in[9];
    const float* ln2g = (const float*)d_in[10];
    const float* ln2b = (const float*)d_in[11];
    const int*   mnp  = (const int*)d_in[12];
    const int*   mbt  = (const int*)d_in[13];

    float *gx, *gh, *gqkv, *gatt, *gmlp, *wqkv, *wout, *w1, *w2;
    cudaGetSymbolAddress((void**)&gx,   g_x);
    cudaGetSymbolAddress((void**)&gh,   g_h);
    cudaGetSymbolAddress((void**)&gqkv, g_qkv);
    cudaGetSymbolAddress((void**)&gatt, g_att);
    cudaGetSymbolAddress((void**)&gmlp, g_mlp);
    cudaGetSymbolAddress((void**)&wqkv, g_wqkv);
    cudaGetSymbolAddress((void**)&wout, g_wout);
    cudaGetSymbolAddress((void**)&w1,   g_w1);
    cudaGetSymbolAddress((void**)&w2,   g_w2);

    cudaFuncSetAttribute(tgemm<1>, cudaFuncAttributeMaxDynamicSharedMemorySize, SMTOT);
    cudaFuncSetAttribute(tgemm<2>, cudaFuncAttributeMaxDynamicSharedMemorySize, SMTOT);
    cudaFuncSetAttribute(tgemm<3>, cudaFuncAttributeMaxDynamicSharedMemorySize, SMTOT);

    // transpose + round weights:  [K][N] -> [N][K]
    tr_kernel<<<dim3(QKV3/32, DIMM/32, DEPTH), dim3(32,8)>>>(Wqkv, wqkv, DIMM, QKV3);
    tr_kernel<<<dim3(DIMM/32, INNER/32, DEPTH), dim3(32,8)>>>(Wout, wout, INNER, DIMM);
    tr_kernel<<<dim3(MLPD/32, DIMM/32, DEPTH), dim3(32,8)>>>(W1,   w1,   DIMM, MLPD);
    tr_kernel<<<dim3(DIMM/32, MLPD/32, DEPTH), dim3(32,8)>>>(W2,   w2,   MLPD, DIMM);

    cudaMemcpyAsync(gx, x, (size_t)TOK * DIMM * sizeof(float),
                    cudaMemcpyDeviceToDevice);

    for (int l = 0; l < DEPTH; l++) {
        ln_kernel<<<TOK, 256>>>(gx, gh, ln1g + l*DIMM, ln1b + l*DIMM);
        tgemm<3><<<dim3(QKV3/128, TOK/128), 256, SMTOT>>>(
            gh, wqkv + (size_t)l*QKV3*DIMM, gqkv, nullptr, nullptr,
            TOK, QKV3, DIMM);
        flash_kernel<<<dim3(SEQ/128, BATCH*HEADS), 256>>>(gqkv, gatt, mnp, mbt);
        tgemm<2><<<dim3(DIMM/128, TOK/128), 256, SMTOT>>>(
            gatt, wout + (size_t)l*DIMM*INNER, gx, bout + l*DIMM, gx,
            TOK, DIMM, INNER);
        ln_kernel<<<TOK, 256>>>(gx, gh, ln2g + l*DIMM, ln2b + l*DIMM);
        tgemm<1><<<dim3(MLPD/128, TOK/128), 256, SMTOT>>>(
            gh, w1 + (size_t)l*MLPD*DIMM, gmlp, b1 + l*MLPD, nullptr,
            TOK, MLPD, DIMM);
        tgemm<2><<<dim3(DIMM/128, TOK/128), 256, SMTOT>>>(
            gmlp, w2 + (size_t)l*DIMM*MLPD, gx, b2 + l*DIMM, gx,
            TOK, DIMM, MLPD);
    }

    cudaMemcpyAsync(d_out, gx, (size_t)TOK * DIMM * sizeof(float),
                    cudaMemcpyDeviceToDevice);
}

// round 8
// speedup vs baseline: 2.4261x; 1.8011x over previous
#include <cuda_runtime.h>
#include <cuda_fp16.h>
#include <math.h>
#include <stdint.h>

#define DIMM   1024
#define DEPTH  4
#define HEADS  16
#define DHEAD  64
#define MLPD   4096
#define INNER  1024
#define BATCH  4
#define SEQ    1024
#define TOK    (BATCH*SEQ)
#define QKV3   (3*INNER)

// ---------------- scratch ----------------------------------------------------
__device__ float  g_x  [TOK*DIMM];                 // residual stream (f32)
__device__ __half g_h  [TOK*DIMM];                 // LN output (fp16)
__device__ __half g_qkv[TOK*QKV3];
__device__ __half g_att[TOK*INNER];
__device__ __half g_mlp[TOK*MLPD];
// transposed fp16 weights, per layer stored [N][K]
__device__ __half g_wqkv[(size_t)DEPTH*QKV3*DIMM];
__device__ __half g_wout[(size_t)DEPTH*DIMM*INNER];
__device__ __half g_w1  [(size_t)DEPTH*MLPD*DIMM];
__device__ __half g_w2  [(size_t)DEPTH*MLPD*DIMM];

__device__ __forceinline__ uint32_t smem_u32(const void* p){
    return (uint32_t)__cvta_generic_to_shared(p);
}
__device__ __forceinline__ uint32_t ph(float a, float b){
    __half2 h = __floats2half2_rn(a, b);
    return *reinterpret_cast<uint32_t*>(&h);
}
#define CP16(dst, src) asm volatile("cp.async.cg.shared.global [%0], [%1], 16;\n" :: "r"(dst), "l"(src))
#define CP_COMMIT()    asm volatile("cp.async.commit_group;\n" ::: "memory")
#define CP_WAIT1()     asm volatile("cp.async.wait_group 1;\n" ::: "memory")
#define CP_WAIT0()     asm volatile("cp.async.wait_group 0;\n" ::: "memory")

#define MMA_F16(d, a, b) \
  asm volatile("mma.sync.aligned.m16n8k16.row.col.f32.f16.f16.f32 " \
    "{%0,%1,%2,%3},{%4,%5,%6,%7},{%8,%9},{%0,%1,%2,%3};" \
    : "+f"((d)[0]),"+f"((d)[1]),"+f"((d)[2]),"+f"((d)[3]) \
    : "r"((a)[0]),"r"((a)[1]),"r"((a)[2]),"r"((a)[3]),"r"((b)[0]),"r"((b)[1]))

__device__ __forceinline__ void ldsm_x4(uint32_t* r, uint32_t a){
    asm volatile("ldmatrix.sync.aligned.m8n8.x4.shared.b16 {%0,%1,%2,%3}, [%4];"
        : "=r"(r[0]),"=r"(r[1]),"=r"(r[2]),"=r"(r[3]) : "r"(a));
}
__device__ __forceinline__ void ldsm_x2(uint32_t* r, uint32_t a){
    asm volatile("ldmatrix.sync.aligned.m8n8.x2.shared.b16 {%0,%1}, [%2];"
        : "=r"(r[0]),"=r"(r[1]) : "r"(a));
}
__device__ __forceinline__ void ldsm_x4t(uint32_t* r, uint32_t a){
    asm volatile("ldmatrix.sync.aligned.m8n8.x4.trans.shared.b16 {%0,%1,%2,%3}, [%4];"
        : "=r"(r[0]),"=r"(r[1]),"=r"(r[2]),"=r"(r[3]) : "r"(a));
}

// ---------------- weight transpose + fp16 round ------------------------------
// in: [DEPTH][K][N] f32  ->  out: [DEPTH][N][K] fp16
__global__ void tr_kernel(const float* __restrict__ in, __half* __restrict__ out,
                          int K, int N)
{
    __shared__ float t[32][33];
    const int l = blockIdx.z;
    const float* src = in + (size_t)l*K*N;
    __half* dst = out + (size_t)l*K*N;
    const int k0 = blockIdx.y*32, n0 = blockIdx.x*32;
    const int tx = threadIdx.x, ty = threadIdx.y;
    #pragma unroll
    for (int r = ty; r < 32; r += 8)
        t[r][tx] = src[(size_t)(k0+r)*N + n0+tx];
    __syncthreads();
    #pragma unroll
    for (int r = ty; r < 32; r += 8)
        dst[(size_t)(n0+r)*K + k0+tx] = __float2half_rn(t[tx][r]);
}

// ---------------- LayerNorm (f32 in, fp16 out) -------------------------------
__global__ void ln_kernel(const float* __restrict__ in, __half* __restrict__ out,
                          const float* __restrict__ gg, const float* __restrict__ bb)
{
    __shared__ float sh[8], sh2[8];
    int row = blockIdx.x;
    int tid = threadIdx.x;
    const float4 xv = ((const float4*)(in + (size_t)row*DIMM))[tid];
    float s  = xv.x + xv.y + xv.z + xv.w;
    float s2 = xv.x*xv.x + xv.y*xv.y + xv.z*xv.z + xv.w*xv.w;
    #pragma unroll
    for (int o = 16; o > 0; o >>= 1) {
        s  += __shfl_xor_sync(0xffffffffu, s,  o);
        s2 += __shfl_xor_sync(0xffffffffu, s2, o);
    }
    if ((tid & 31) == 0) { sh[tid>>5] = s; sh2[tid>>5] = s2; }
    __syncthreads();
    s  = sh[0]+sh[1]+sh[2]+sh[3]+sh[4]+sh[5]+sh[6]+sh[7];
    s2 = sh2[0]+sh2[1]+sh2[2]+sh2[3]+sh2[4]+sh2[5]+sh2[6]+sh2[7];
    float mean = s * (1.0f/DIMM);
    float var  = s2 * (1.0f/DIMM) - mean*mean;
    float rs   = rsqrtf(var + 1e-5f);
    const float4 gv = ((const float4*)gg)[tid];
    const float4 bv = ((const float4*)bb)[tid];
    uint2 o;
    o.x = ph((xv.x - mean)*rs*gv.x + bv.x, (xv.y - mean)*rs*gv.y + bv.y);
    o.y = ph((xv.z - mean)*rs*gv.z + bv.z, (xv.w - mean)*rs*gv.w + bv.w);
    ((uint2*)(out + (size_t)row*DIMM))[tid] = o;
}

// ---------------- FP16 GEMM: BK=64, 3-stage cp.async, ldmatrix ---------------
// C = A[M,K] @ Bt[Nn,K]^T, fp16 in, f32 accum.
// Smem rows: 64 k halves = 128 B + 16 pad = 144 B. 8 warps, warp tile 64x32.
// EPI: 1 +bias+GELU -> fp16 ; 2 +bias+residual -> f32 ; 3 plain -> fp16
#define ABYH  (128*144)        // 18432 B per operand tile
#define STGH  (2*ABYH)         // 36864
#define NSTG  3
#define SMTOT (NSTG*STGH)      // 110592

template<int EPI>
__global__ void __launch_bounds__(256, 2)
hgemm(const __half* __restrict__ A, const __half* __restrict__ Bt,
      void* __restrict__ Cv, const float* __restrict__ bias,
      const float* __restrict__ R, int M, int Nn, int K)
{
    extern __shared__ char smc[];
    const uint32_t sb = smem_u32(smc);
    const int tid = threadIdx.x, warp = tid >> 5, lane = tid & 31;
    const int g = lane >> 2, t = lane & 3;
    const int wm = (warp >> 2) * 64;
    const int wn = (warp & 3) * 32;
    const int brow = blockIdx.y * 128;
    const int bcol = blockIdx.x * 128;

    float acc[4][4][4];
    #pragma unroll
    for (int i = 0; i < 4; i++)
      #pragma unroll
      for (int j = 0; j < 4; j++)
        { acc[i][j][0]=0.f; acc[i][j][1]=0.f; acc[i][j][2]=0.f; acc[i][j][3]=0.f; }

    // 128 rows x 8 chunks (16B = 8 halves) per operand = 1024 chunks; 4/thr each
    auto prefetch = [&](int blk){
        const uint32_t ab = sb + (uint32_t)((blk % NSTG) * STGH);
        const uint32_t bb = ab + ABYH;
        const int kof = blk * 64;
        #pragma unroll
        for (int j = 0; j < 4; j++){
            const int c = tid + j*256;
            const int row = c >> 3, q = c & 7;
            CP16(ab + (uint32_t)(row*144 + q*16), A  + (size_t)(brow+row)*K + kof + q*8);
            CP16(bb + (uint32_t)(row*144 + q*16), Bt + (size_t)(bcol+row)*K + kof + q*8);
        }
    };

    prefetch(0); CP_COMMIT();
    prefetch(1); CP_COMMIT();

    const uint32_t aoff = (uint32_t)((wm + (lane & 15))*144 + (lane >> 4)*16);
    const uint32_t boff = (uint32_t)((wn + (lane & 7))*144 + ((lane >> 3) & 1)*16) + ABYH;

    const int nk = K >> 6;
    for (int i = 0; i < nk; i++){
        CP_WAIT1();
        __syncthreads();
        const uint32_t stg = sb + (uint32_t)((i % NSTG) * STGH);
        #pragma unroll
        for (int s = 0; s < 4; s++){            // 4 k16 slices (32 B each)
            uint32_t af[4][4], bf[4][2];
            #pragma unroll
            for (int mt = 0; mt < 4; mt++)
                ldsm_x4(af[mt], stg + aoff + (uint32_t)(mt*2304 + s*32));
            #pragma unroll
            for (int nt = 0; nt < 4; nt++)
                ldsm_x2(bf[nt], stg + boff + (uint32_t)(nt*1152 + s*32));
            #pragma unroll
            for (int mt = 0; mt < 4; mt++)
              #pragma unroll
              for (int nt = 0; nt < 4; nt++)
                MMA_F16(acc[mt][nt], af[mt], bf[nt]);
        }
        if (i + 2 < nk) prefetch(i + 2);
        CP_COMMIT();
    }

    #pragma unroll
    for (int mt = 0; mt < 4; mt++){
        const int r0 = brow + wm + mt*16 + g;
        #pragma unroll
        for (int nt = 0; nt < 4; nt++){
            const int c = bcol + wn + nt*8 + 2*t;
            float v[4] = {acc[mt][nt][0], acc[mt][nt][1], acc[mt][nt][2], acc[mt][nt][3]};
            if (EPI == 1 || EPI == 2){
                const float b0 = bias[c], b1 = bias[c+1];
                v[0]+=b0; v[1]+=b1; v[2]+=b0; v[3]+=b1;
            }
            if (EPI == 1){
                #pragma unroll
                for (int q = 0; q < 4; q++)
                    v[q] = 0.5f * v[q] * (1.0f + erff(v[q] * 0.70710678118654752f));
            }
            if (EPI == 2){
                float* Cf = (float*)Cv;
                const float2 r0v = *(const float2*)(R + (size_t)r0*Nn + c);
                const float2 r1v = *(const float2*)(R + (size_t)(r0+8)*Nn + c);
                float2 o0 = {v[0]+r0v.x, v[1]+r0v.y}, o1 = {v[2]+r1v.x, v[3]+r1v.y};
                *(float2*)(Cf + (size_t)r0    *Nn + c) = o0;
                *(float2*)(Cf + (size_t)(r0+8)*Nn + c) = o1;
            } else {
                __half* Ch = (__half*)Cv;
                *(uint32_t*)(Ch + (size_t)r0    *Nn + c) = ph(v[0], v[1]);
                *(uint32_t*)(Ch + (size_t)(r0+8)*Nn + c) = ph(v[2], v[3]);
            }
        }
    }
}

// ---------------- Fused fp16 flash attention ---------------------------------
// grid (SEQ/128, B*H), 256 thr. Warp w owns 16 query rows. No P shuffles:
// S C-fragment packs directly into PV A-fragment (fp16 property).
__global__ void __launch_bounds__(256, 2)
flash_kernel(const __half* __restrict__ qkv, __half* __restrict__ att,
             const int* __restrict__ mnp, const int* __restrict__ mbt)
{
    __shared__ __half Ks[64*72];   // 72 halves = 144 B rows
    __shared__ __half Vs[64*72];
    __shared__ float cmask[SEQ];

    const int tid = threadIdx.x, warp = tid >> 5, lane = tid & 31;
    const int g = lane >> 2, t = lane & 3;
    const int bh = blockIdx.y, b = bh >> 4, h = bh & 15;
    const int i0 = blockIdx.x * 128;

    const __half* qb    = qkv + (size_t)(b*SEQ + i0) * QKV3 + h*DHEAD;
    const __half* kbase = qkv + (size_t)(b*SEQ) * QKV3 + INNER   + h*DHEAD;
    const __half* vbase = qkv + (size_t)(b*SEQ) * QKV3 + 2*INNER + h*DHEAD;

    const uint32_t ks_b = smem_u32(Ks);
    const uint32_t vs_b = smem_u32(Vs);

    {
        const int j = tid * 4;
        const int4 a = *(const int4*)(mnp + b*SEQ + j);
        const int4 c = *(const int4*)(mbt + b*SEQ + j);
        cmask[j+0] = (a.x != 0 && c.x != 1) ? 1.f : 0.f;
        cmask[j+1] = (a.y != 0 && c.y != 1) ? 1.f : 0.f;
        cmask[j+2] = (a.z != 0 && c.z != 1) ? 1.f : 0.f;
        cmask[j+3] = (a.w != 0 && c.w != 1) ? 1.f : 0.f;
    }

    // stage Q (128 rows x 64 halves = 8 chunks/row) into Ks/Vs
    #pragma unroll
    for (int it = 0; it < 4; it++){
        const int idx = tid + it*256;
        const int r = idx >> 3, q = idx & 7;
        const uint32_t dst = (r < 64) ? (ks_b + (uint32_t)(r*144 + q*16))
                                      : (vs_b + (uint32_t)((r-64)*144 + q*16));
        CP16(dst, qb + (size_t)r*QKV3 + q*8);
    }
    CP_COMMIT(); CP_WAIT0();
    __syncthreads();

    // Q A-fragments: 4 k16 slices of d=64
    uint32_t qa[4][4];
    {
        const uint32_t base = (warp < 4) ? ks_b : vs_b;
        const int row0 = (warp & 3) * 16;
        #pragma unroll
        for (int kc = 0; kc < 4; kc++)
            ldsm_x4(qa[kc], base + (uint32_t)((row0 + (lane & 15))*144
                                              + (lane >> 4)*16 + kc*32));
    }

    const int qrow = i0 + warp*16;
    const bool rm0 = (mnp[b*SEQ + qrow + g    ] == 0);
    const bool rm1 = (mnp[b*SEQ + qrow + g + 8] == 0);

    float m0 = -1e30f, m1 = -1e30f, l0 = 0.f, l1 = 0.f;
    float o[8][4];
    #pragma unroll
    for (int nt = 0; nt < 8; nt++){ o[nt][0]=0.f; o[nt][1]=0.f; o[nt][2]=0.f; o[nt][3]=0.f; }

    for (int jt = 0; jt < 16; jt++){
        __syncthreads();
        #pragma unroll
        for (int it = 0; it < 2; it++){
            const int idx = tid + it*256;          // 512 chunks per operand
            const int r = idx >> 3, q = idx & 7;
            const size_t gr = (size_t)(jt*64 + r) * QKV3 + q*8;
            CP16(ks_b + (uint32_t)(r*144 + q*16), kbase + gr);
            CP16(vs_b + (uint32_t)(r*144 + q*16), vbase + gr);
        }
        CP_COMMIT(); CP_WAIT0();
        __syncthreads();

        // S = Q K^T over 64-col tile
        float s[8][4];
        #pragma unroll
        for (int nc = 0; nc < 8; nc++){ s[nc][0]=0.f; s[nc][1]=0.f; s[nc][2]=0.f; s[nc][3]=0.f; }
        #pragma unroll
        for (int kc = 0; kc < 4; kc++){
            #pragma unroll
            for (int np = 0; np < 4; np++){        // nc pairs via x4
                uint32_t kf[4];
                ldsm_x4(kf, ks_b + (uint32_t)((np*16 + (lane >> 4)*8 + (lane & 7))*144
                                              + ((lane >> 3) & 1)*16 + kc*32));
                MMA_F16(s[np*2    ], qa[kc], kf);      // kf[0],kf[1]
                MMA_F16(s[np*2 + 1], qa[kc], kf + 2);  // kf[2],kf[3]
            }
        }

        // mask + scale + row max
        float mx0 = -1e30f, mx1 = -1e30f;
        #pragma unroll
        for (int nc = 0; nc < 8; nc++){
            const int j = jt*64 + nc*8 + 2*t;
            const float c0v = cmask[j], c1v = cmask[j+1];
            s[nc][0] = (rm0 || c0v == 0.f) ? -1000.f : s[nc][0]*0.125f;
            s[nc][1] = (rm0 || c1v == 0.f) ? -1000.f : s[nc][1]*0.125f;
            s[nc][2] = (rm1 || c0v == 0.f) ? -1000.f : s[nc][2]*0.125f;
            s[nc][3] = (rm1 || c1v == 0.f) ? -1000.f : s[nc][3]*0.125f;
            mx0 = fmaxf(mx0, fmaxf(s[nc][0], s[nc][1]));
            mx1 = fmaxf(mx1, fmaxf(s[nc][2], s[nc][3]));
        }
        mx0 = fmaxf(mx0, __shfl_xor_sync(0xffffffffu, mx0, 1));
        mx0 = fmaxf(mx0, __shfl_xor_sync(0xffffffffu, mx0, 2));
        mx1 = fmaxf(mx1, __shfl_xor_sync(0xffffffffu, mx1, 1));
        mx1 = fmaxf(mx1, __shfl_xor_sync(0xffffffffu, mx1, 2));

        const float nm0 = fmaxf(m0, mx0), nm1 = fmaxf(m1, mx1);
        const float a0 = __expf(m0 - nm0), a1 = __expf(m1 - nm1);

        float r0s = 0.f, r1s = 0.f;
        uint32_t pbh[8][2];
        #pragma unroll
        for (int nc = 0; nc < 8; nc++){
            const float e0 = __expf(s[nc][0] - nm0);
            const float e1 = __expf(s[nc][1] - nm0);
            const float e2 = __expf(s[nc][2] - nm1);
            const float e3 = __expf(s[nc][3] - nm1);
            r0s += e0 + e1; r1s += e2 + e3;
            pbh[nc][0] = ph(e0, e1);               // rows g   : PV a-frag lo
            pbh[nc][1] = ph(e2, e3);               // rows g+8
        }
        r0s += __shfl_xor_sync(0xffffffffu, r0s, 1);
        r0s += __shfl_xor_sync(0xffffffffu, r0s, 2);
        r1s += __shfl_xor_sync(0xffffffffu, r1s, 1);
        r1s += __shfl_xor_sync(0xffffffffu, r1s, 2);

        l0 = l0*a0 + r0s; l1 = l1*a1 + r1s;
        m0 = nm0; m1 = nm1;

        #pragma unroll
        for (int nt = 0; nt < 8; nt++){
            o[nt][0] *= a0; o[nt][1] *= a0;
            o[nt][2] *= a1; o[nt][3] *= a1;
        }

        // O += P @ V  (A-frag direct from pbh, B via ldmatrix.trans)
        #pragma unroll
        for (int kc2 = 0; kc2 < 4; kc2++){
            uint32_t af[4] = {pbh[2*kc2][0], pbh[2*kc2][1],
                              pbh[2*kc2+1][0], pbh[2*kc2+1][1]};
            #pragma unroll
            for (int np = 0; np < 4; np++){
                uint32_t vb[4];
                ldsm_x4t(vb, vs_b + (uint32_t)((kc2*16 + ((lane >> 3) & 1)*8 + (lane & 7))*144
                                               + (np*2 + (lane >> 4))*16));
                MMA_F16(o[np*2    ], af, vb);
                MMA_F16(o[np*2 + 1], af, vb + 2);
            }
        }
    }

    const float inv0 = 1.0f / l0, inv1 = 1.0f / l1;
    const size_t r0 = (size_t)(b*SEQ + qrow + g);
    #pragma unroll
    for (int nt = 0; nt < 8; nt++){
        const int c = h*DHEAD + nt*8 + 2*t;
        *(uint32_t*)(att + r0      * INNER + c) = ph(o[nt][0]*inv0, o[nt][1]*inv0);
        *(uint32_t*)(att + (r0 + 8) * INNER + c) = ph(o[nt][2]*inv1, o[nt][3]*inv1);
    }
}

// ---------------------------------------------------------------------------
extern "C" void kernel_launch(void* const* d_in, const int* in_sizes, int n_in,
                              void* d_out, int out_size)
{
    const float* x    = (const float*)d_in[0];
    const float* Wqkv = (const float*)d_in[1];
    const float* Wout = (const float*)d_in[2];
    const float* bout = (const float*)d_in[3];
    const float* ln1g = (const float*)d_in[4];
    const float* ln1b = (const float*)d_in[5];
    const float* W1   = (const float*)d_in[6];
    const float* b1   = (const float*)d_in[7];
    const float* W2   = (const float*)d_in[8];
    const float* b2   = (const float*)d_in[9];
    const float* ln2g = (const float*)d_in[10];
    const float* ln2b = (const float*)d_in[11];
    const int*   mnp  = (const int*)d_in[12];
    const int*   mbt  = (const int*)d_in[13];

    float *gx;
    __half *gh, *gqkv, *gatt, *gmlp, *wqkv, *wout, *w1, *w2;
    cudaGetSymbolAddress((void**)&gx,   g_x);
    cudaGetSymbolAddress((void**)&gh,   g_h);
    cudaGetSymbolAddress((void**)&gqkv, g_qkv);
    cudaGetSymbolAddress((void**)&gatt, g_att);
    cudaGetSymbolAddress((void**)&gmlp, g_mlp);
    cudaGetSymbolAddress((void**)&wqkv, g_wqkv);
    cudaGetSymbolAddress((void**)&wout, g_wout);
    cudaGetSymbolAddress((void**)&w1,   g_w1);
    cudaGetSymbolAddress((void**)&w2,   g_w2);

    cudaFuncSetAttribute(hgemm<1>, cudaFuncAttributeMaxDynamicSharedMemorySize, SMTOT);
    cudaFuncSetAttribute(hgemm<2>, cudaFuncAttributeMaxDynamicSharedMemorySize, SMTOT);
    cudaFuncSetAttribute(hgemm<3>, cudaFuncAttributeMaxDynamicSharedMemorySize, SMTOT);

    // transpose + fp16-round weights: [K][N] -> [N][K]
    tr_kernel<<<dim3(QKV3/32, DIMM/32, DEPTH), dim3(32,8)>>>(Wqkv, wqkv, DIMM, QKV3);
    tr_kernel<<<dim3(DIMM/32, INNER/32, DEPTH), dim3(32,8)>>>(Wout, wout, INNER, DIMM);
    tr_kernel<<<dim3(MLPD/32, DIMM/32, DEPTH), dim3(32,8)>>>(W1,   w1,   DIMM, MLPD);
    tr_kernel<<<dim3(DIMM/32, MLPD/32, DEPTH), dim3(32,8)>>>(W2,   w2,   MLPD, DIMM);

    cudaMemcpyAsync(gx, x, (size_t)TOK * DIMM * sizeof(float),
                    cudaMemcpyDeviceToDevice);

    for (int l = 0; l < DEPTH; l++) {
        ln_kernel<<<TOK, 256>>>(gx, gh, ln1g + l*DIMM, ln1b + l*DIMM);
        hgemm<3><<<dim3(QKV3/128, TOK/128), 256, SMTOT>>>(
            gh, wqkv + (size_t)l*QKV3*DIMM, gqkv, nullptr, nullptr,
            TOK, QKV3, DIMM);
        flash_kernel<<<dim3(SEQ/128, BATCH*HEADS), 256>>>(gqkv, gatt, mnp, mbt);
        hgemm<2><<<dim3(DIMM/128, TOK/128), 256, SMTOT>>>(
            gatt, wout + (size_t)l*DIMM*INNER, gx, bout + l*DIMM, gx,
            TOK, DIMM, INNER);
        ln_kernel<<<TOK, 256>>>(gx, gh, ln2g + l*DIMM, ln2b + l*DIMM);
        hgemm<1><<<dim3(MLPD/128, TOK/128), 256, SMTOT>>>(
            gh, w1 + (size_t)l*MLPD*DIMM, gmlp, b1 + l*MLPD, nullptr,
            TOK, MLPD, DIMM);
        hgemm<2><<<dim3(DIMM/128, TOK/128), 256, SMTOT>>>(
            gmlp, w2 + (size_t)l*MLPD*DIMM, gx, b2 + l*DIMM, gx,
            TOK, DIMM, MLPD);
    }

    cudaMemcpyAsync(d_out, gx, (size_t)TOK * DIMM * sizeof(float),
                    cudaMemcpyDeviceToDevice);
}

// round 9
// speedup vs baseline: 2.5741x; 1.0610x over previous
#include <cuda_runtime.h>
#include <cuda_fp16.h>
#include <math.h>
#include <stdint.h>

#define DIMM   1024
#define DEPTH  4
#define HEADS  16
#define DHEAD  64
#define MLPD   4096
#define INNER  1024
#define BATCH  4
#define SEQ    1024
#define TOK    (BATCH*SEQ)
#define QKV3   (3*INNER)

// ---------------- scratch ----------------------------------------------------
__device__ float  g_x  [TOK*DIMM];                 // residual stream (f32)
__device__ __half g_h  [TOK*DIMM];                 // LN output (fp16)
__device__ __half g_qkv[TOK*QKV3];
__device__ __half g_att[TOK*INNER];
__device__ __half g_mlp[TOK*MLPD];
// fp16 weights, ORIGINAL [K][N] layout (no transpose)
__device__ __half g_wqkv[(size_t)DEPTH*DIMM*QKV3];
__device__ __half g_wout[(size_t)DEPTH*INNER*DIMM];
__device__ __half g_w1  [(size_t)DEPTH*DIMM*MLPD];
__device__ __half g_w2  [(size_t)DEPTH*MLPD*DIMM];

__device__ __forceinline__ uint32_t smem_u32(const void* p){
    return (uint32_t)__cvta_generic_to_shared(p);
}
__device__ __forceinline__ uint32_t ph(float a, float b){
    __half2 h = __floats2half2_rn(a, b);
    return *reinterpret_cast<uint32_t*>(&h);
}
#define CP16(dst, src) asm volatile("cp.async.cg.shared.global [%0], [%1], 16;\n" :: "r"(dst), "l"(src))
#define CP_COMMIT()    asm volatile("cp.async.commit_group;\n" ::: "memory")
#define CP_WAIT1()     asm volatile("cp.async.wait_group 1;\n" ::: "memory")
#define CP_WAIT0()     asm volatile("cp.async.wait_group 0;\n" ::: "memory")

#define MMA_F16(d, a, b) \
  asm volatile("mma.sync.aligned.m16n8k16.row.col.f32.f16.f16.f32 " \
    "{%0,%1,%2,%3},{%4,%5,%6,%7},{%8,%9},{%0,%1,%2,%3};" \
    : "+f"((d)[0]),"+f"((d)[1]),"+f"((d)[2]),"+f"((d)[3]) \
    : "r"((a)[0]),"r"((a)[1]),"r"((a)[2]),"r"((a)[3]),"r"((b)[0]),"r"((b)[1]))

__device__ __forceinline__ void ldsm_x4(uint32_t* r, uint32_t a){
    asm volatile("ldmatrix.sync.aligned.m8n8.x4.shared.b16 {%0,%1,%2,%3}, [%4];"
        : "=r"(r[0]),"=r"(r[1]),"=r"(r[2]),"=r"(r[3]) : "r"(a));
}
__device__ __forceinline__ void ldsm_x4t(uint32_t* r, uint32_t a){
    asm volatile("ldmatrix.sync.aligned.m8n8.x4.trans.shared.b16 {%0,%1,%2,%3}, [%4];"
        : "=r"(r[0]),"=r"(r[1]),"=r"(r[2]),"=r"(r[3]) : "r"(a));
}

// ---------------- streaming f32 -> fp16 convert ------------------------------
__global__ void cvt16(const float* __restrict__ in, __half* __restrict__ out, int n4)
{
    int i = blockIdx.x * blockDim.x + threadIdx.x;
    if (i < n4){
        const float4 v = ((const float4*)in)[i];
        uint2 o; o.x = ph(v.x, v.y); o.y = ph(v.z, v.w);
        ((uint2*)out)[i] = o;
    }
}

// ---------------- LayerNorm (f32 in, fp16 out) -------------------------------
__global__ void ln_kernel(const float* __restrict__ in, __half* __restrict__ out,
                          const float* __restrict__ gg, const float* __restrict__ bb)
{
    __shared__ float sh[8], sh2[8];
    int row = blockIdx.x;
    int tid = threadIdx.x;
    const float4 xv = ((const float4*)(in + (size_t)row*DIMM))[tid];
    float s  = xv.x + xv.y + xv.z + xv.w;
    float s2 = xv.x*xv.x + xv.y*xv.y + xv.z*xv.z + xv.w*xv.w;
    #pragma unroll
    for (int o = 16; o > 0; o >>= 1) {
        s  += __shfl_xor_sync(0xffffffffu, s,  o);
        s2 += __shfl_xor_sync(0xffffffffu, s2, o);
    }
    if ((tid & 31) == 0) { sh[tid>>5] = s; sh2[tid>>5] = s2; }
    __syncthreads();
    s  = sh[0]+sh[1]+sh[2]+sh[3]+sh[4]+sh[5]+sh[6]+sh[7];
    s2 = sh2[0]+sh2[1]+sh2[2]+sh2[3]+sh2[4]+sh2[5]+sh2[6]+sh2[7];
    float mean = s * (1.0f/DIMM);
    float var  = s2 * (1.0f/DIMM) - mean*mean;
    float rs   = rsqrtf(var + 1e-5f);
    const float4 gv = ((const float4*)gg)[tid];
    const float4 bv = ((const float4*)bb)[tid];
    uint2 o;
    o.x = ph((xv.x - mean)*rs*gv.x + bv.x, (xv.y - mean)*rs*gv.y + bv.y);
    o.y = ph((xv.z - mean)*rs*gv.z + bv.z, (xv.w - mean)*rs*gv.w + bv.w);
    ((uint2*)(out + (size_t)row*DIMM))[tid] = o;
}

// ---------------- FP16 GEMM: B in [K][N], ldmatrix.trans, BK=64, 3-stage -----
// C = A[M,K] @ B[K,Nn].  A smem [128 m][64 k] 144 B rows; B smem [64 k][128 n] 272 B rows.
// EPI: 1 +bias+GELU -> fp16 ; 2 +bias+residual -> f32 ; 3 plain -> fp16
#define ABYH  18432            // 128*144
#define BBYH  17408            // 64*272
#define STGH  (ABYH+BBYH)      // 35840
#define NSTG  3
#define SMTOT (NSTG*STGH)      // 107520

template<int EPI>
__global__ void __launch_bounds__(256, 2)
hgemm(const __half* __restrict__ A, const __half* __restrict__ B,
      void* __restrict__ Cv, const float* __restrict__ bias,
      const float* __restrict__ R, int M, int Nn, int K)
{
    extern __shared__ char smc[];
    const uint32_t sb = smem_u32(smc);
    const int tid = threadIdx.x, warp = tid >> 5, lane = tid & 31;
    const int g = lane >> 2, t = lane & 3;
    const int wm = (warp >> 2) * 64;
    const int wn = (warp & 3) * 32;
    const int brow = blockIdx.y * 128;
    const int bcol = blockIdx.x * 128;

    float acc[4][4][4];
    #pragma unroll
    for (int i = 0; i < 4; i++)
      #pragma unroll
      for (int j = 0; j < 4; j++)
        { acc[i][j][0]=0.f; acc[i][j][1]=0.f; acc[i][j][2]=0.f; acc[i][j][3]=0.f; }

    auto prefetch = [&](int blk){
        const uint32_t ab = sb + (uint32_t)((blk % NSTG) * STGH);
        const uint32_t bb = ab + ABYH;
        const int kof = blk * 64;
        #pragma unroll
        for (int j = 0; j < 4; j++){
            const int c = tid + j*256;
            // A: 128 rows x 8 chunks
            const int ar = c >> 3, aq = c & 7;
            CP16(ab + (uint32_t)(ar*144 + aq*16), A + (size_t)(brow+ar)*K + kof + aq*8);
            // B: 64 rows x 16 chunks
            const int br2 = c >> 4, bq = c & 15;
            CP16(bb + (uint32_t)(br2*272 + bq*16), B + (size_t)(kof+br2)*Nn + bcol + bq*8);
        }
    };

    prefetch(0); CP_COMMIT();
    prefetch(1); CP_COMMIT();

    const uint32_t aoff = (uint32_t)((wm + (lane & 15))*144 + (lane >> 4)*16);
    // B trans-ldsm lane address: row = s*16 + (lane&15), col = wn + np*16 + ((lane>>4)&1)*8
    const uint32_t boffl = (uint32_t)((lane & 15)*272 + (wn + ((lane >> 4) & 1)*8)*2) + ABYH;

    const int nk = K >> 6;
    for (int i = 0; i < nk; i++){
        CP_WAIT1();
        __syncthreads();
        const uint32_t stg = sb + (uint32_t)((i % NSTG) * STGH);
        #pragma unroll
        for (int s = 0; s < 4; s++){            // 4 k16 slices
            uint32_t af[4][4], bq2[2][4];
            #pragma unroll
            for (int mt = 0; mt < 4; mt++)
                ldsm_x4(af[mt], stg + aoff + (uint32_t)(mt*2304 + s*32));
            #pragma unroll
            for (int np = 0; np < 2; np++)
                ldsm_x4t(bq2[np], stg + boffl + (uint32_t)(s*4352 + np*32));
            #pragma unroll
            for (int mt = 0; mt < 4; mt++)
              #pragma unroll
              for (int nt = 0; nt < 4; nt++)
                MMA_F16(acc[mt][nt], af[mt], &bq2[nt >> 1][(nt & 1)*2]);
        }
        if (i + 2 < nk) prefetch(i + 2);
        CP_COMMIT();
    }

    #pragma unroll
    for (int mt = 0; mt < 4; mt++){
        const int r0 = brow + wm + mt*16 + g;
        #pragma unroll
        for (int nt = 0; nt < 4; nt++){
            const int c = bcol + wn + nt*8 + 2*t;
            float v[4] = {acc[mt][nt][0], acc[mt][nt][1], acc[mt][nt][2], acc[mt][nt][3]};
            if (EPI == 1 || EPI == 2){
                const float b0 = bias[c], b1 = bias[c+1];
                v[0]+=b0; v[1]+=b1; v[2]+=b0; v[3]+=b1;
            }
            if (EPI == 1){
                #pragma unroll
                for (int q = 0; q < 4; q++)
                    v[q] = 0.5f * v[q] * (1.0f + erff(v[q] * 0.70710678118654752f));
            }
            if (EPI == 2){
                float* Cf = (float*)Cv;
                const float2 r0v = *(const float2*)(R + (size_t)r0*Nn + c);
                const float2 r1v = *(const float2*)(R + (size_t)(r0+8)*Nn + c);
                float2 o0 = {v[0]+r0v.x, v[1]+r0v.y}, o1 = {v[2]+r1v.x, v[3]+r1v.y};
                *(float2*)(Cf + (size_t)r0    *Nn + c) = o0;
                *(float2*)(Cf + (size_t)(r0+8)*Nn + c) = o1;
            } else {
                __half* Ch = (__half*)Cv;
                *(uint32_t*)(Ch + (size_t)r0    *Nn + c) = ph(v[0], v[1]);
                *(uint32_t*)(Ch + (size_t)(r0+8)*Nn + c) = ph(v[2], v[3]);
            }
        }
    }
}

// ---------------- Fused fp16 flash attention, double-buffered K/V ------------
// Dynamic smem: 3 stages x (K 9216 + V 9216) + cmask 4096 = 59392 B
#define FKV   18432
#define FLSM  (3*FKV + 4096)

__global__ void __launch_bounds__(256, 2)
flash_kernel(const __half* __restrict__ qkv, __half* __restrict__ att,
             const int* __restrict__ mnp, const int* __restrict__ mbt)
{
    extern __shared__ char fsm[];
    const uint32_t base = smem_u32(fsm);
    float* cmask = (float*)(fsm + 3*FKV);

    const int tid = threadIdx.x, warp = tid >> 5, lane = tid & 31;
    const int g = lane >> 2, t = lane & 3;
    const int bh = blockIdx.y, b = bh >> 4, h = bh & 15;
    const int i0 = blockIdx.x * 128;

    const __half* qb    = qkv + (size_t)(b*SEQ + i0) * QKV3 + h*DHEAD;
    const __half* kbase = qkv + (size_t)(b*SEQ) * QKV3 + INNER   + h*DHEAD;
    const __half* vbase = qkv + (size_t)(b*SEQ) * QKV3 + 2*INNER + h*DHEAD;

    {
        const int j = tid * 4;
        const int4 a = *(const int4*)(mnp + b*SEQ + j);
        const int4 c = *(const int4*)(mbt + b*SEQ + j);
        cmask[j+0] = (a.x != 0 && c.x != 1) ? 1.f : 0.f;
        cmask[j+1] = (a.y != 0 && c.y != 1) ? 1.f : 0.f;
        cmask[j+2] = (a.z != 0 && c.z != 1) ? 1.f : 0.f;
        cmask[j+3] = (a.w != 0 && c.w != 1) ? 1.f : 0.f;
    }

    // stage Q (128 rows x 8 chunks) into stage-0 K/V regions
    #pragma unroll
    for (int it = 0; it < 4; it++){
        const int idx = tid + it*256;
        const int r = idx >> 3, q = idx & 7;
        const uint32_t dst = (r < 64) ? (base + (uint32_t)(r*144 + q*16))
                                      : (base + 9216 + (uint32_t)((r-64)*144 + q*16));
        CP16(dst, qb + (size_t)r*QKV3 + q*8);
    }
    CP_COMMIT(); CP_WAIT0();
    __syncthreads();

    uint32_t qa[4][4];
    {
        const uint32_t qbase = (warp < 4) ? base : (base + 9216);
        const int row0 = (warp & 3) * 16;
        #pragma unroll
        for (int kc = 0; kc < 4; kc++)
            ldsm_x4(qa[kc], qbase + (uint32_t)((row0 + (lane & 15))*144
                                               + (lane >> 4)*16 + kc*32));
    }
    __syncthreads();   // qa extracted; stage 0 may now be overwritten

    auto prefetch = [&](int jt){
        const uint32_t kb = base + (uint32_t)((jt % 3) * FKV);
        const uint32_t vb = kb + 9216;
        #pragma unroll
        for (int it = 0; it < 2; it++){
            const int idx = tid + it*256;
            const int r = idx >> 3, q = idx & 7;
            const size_t gr = (size_t)(jt*64 + r) * QKV3 + q*8;
            CP16(kb + (uint32_t)(r*144 + q*16), kbase + gr);
            CP16(vb + (uint32_t)(r*144 + q*16), vbase + gr);
        }
    };
    prefetch(0); CP_COMMIT();
    prefetch(1); CP_COMMIT();

    const int qrow = i0 + warp*16;
    const bool rm0 = (mnp[b*SEQ + qrow + g    ] == 0);
    const bool rm1 = (mnp[b*SEQ + qrow + g + 8] == 0);

    float m0 = -1e30f, m1 = -1e30f, l0 = 0.f, l1 = 0.f;
    float o[8][4];
    #pragma unroll
    for (int nt = 0; nt < 8; nt++){ o[nt][0]=0.f; o[nt][1]=0.f; o[nt][2]=0.f; o[nt][3]=0.f; }

    for (int jt = 0; jt < 16; jt++){
        CP_WAIT1();
        __syncthreads();
        const uint32_t kb = base + (uint32_t)((jt % 3) * FKV);
        const uint32_t vb = kb + 9216;

        // S = Q K^T over 64-col tile
        float s[8][4];
        #pragma unroll
        for (int nc = 0; nc < 8; nc++){ s[nc][0]=0.f; s[nc][1]=0.f; s[nc][2]=0.f; s[nc][3]=0.f; }
        #pragma unroll
        for (int kc = 0; kc < 4; kc++){
            #pragma unroll
            for (int np = 0; np < 4; np++){
                uint32_t kf[4];
                ldsm_x4(kf, kb + (uint32_t)((np*16 + (lane >> 4)*8 + (lane & 7))*144
                                            + ((lane >> 3) & 1)*16 + kc*32));
                MMA_F16(s[np*2    ], qa[kc], kf);
                MMA_F16(s[np*2 + 1], qa[kc], kf + 2);
            }
        }

        float mx0 = -1e30f, mx1 = -1e30f;
        #pragma unroll
        for (int nc = 0; nc < 8; nc++){
            const int j = jt*64 + nc*8 + 2*t;
            const float c0v = cmask[j], c1v = cmask[j+1];
            s[nc][0] = (rm0 || c0v == 0.f) ? -1000.f : s[nc][0]*0.125f;
            s[nc][1] = (rm0 || c1v == 0.f) ? -1000.f : s[nc][1]*0.125f;
            s[nc][2] = (rm1 || c0v == 0.f) ? -1000.f : s[nc][2]*0.125f;
            s[nc][3] = (rm1 || c1v == 0.f) ? -1000.f : s[nc][3]*0.125f;
            mx0 = fmaxf(mx0, fmaxf(s[nc][0], s[nc][1]));
            mx1 = fmaxf(mx1, fmaxf(s[nc][2], s[nc][3]));
        }
        mx0 = fmaxf(mx0, __shfl_xor_sync(0xffffffffu, mx0, 1));
        mx0 = fmaxf(mx0, __shfl_xor_sync(0xffffffffu, mx0, 2));
        mx1 = fmaxf(mx1, __shfl_xor_sync(0xffffffffu, mx1, 1));
        mx1 = fmaxf(mx1, __shfl_xor_sync(0xffffffffu, mx1, 2));

        const float nm0 = fmaxf(m0, mx0), nm1 = fmaxf(m1, mx1);
        const float a0 = __expf(m0 - nm0), a1 = __expf(m1 - nm1);

        float r0s = 0.f, r1s = 0.f;
        uint32_t pbh[8][2];
        #pragma unroll
        for (int nc = 0; nc < 8; nc++){
            const float e0 = __expf(s[nc][0] - nm0);
            const float e1 = __expf(s[nc][1] - nm0);
            const float e2 = __expf(s[nc][2] - nm1);
            const float e3 = __expf(s[nc][3] - nm1);
            r0s += e0 + e1; r1s += e2 + e3;
            pbh[nc][0] = ph(e0, e1);
            pbh[nc][1] = ph(e2, e3);
        }
        r0s += __shfl_xor_sync(0xffffffffu, r0s, 1);
        r0s += __shfl_xor_sync(0xffffffffu, r0s, 2);
        r1s += __shfl_xor_sync(0xffffffffu, r1s, 1);
        r1s += __shfl_xor_sync(0xffffffffu, r1s, 2);

        l0 = l0*a0 + r0s; l1 = l1*a1 + r1s;
        m0 = nm0; m1 = nm1;

        #pragma unroll
        for (int nt = 0; nt < 8; nt++){
            o[nt][0] *= a0; o[nt][1] *= a0;
            o[nt][2] *= a1; o[nt][3] *= a1;
        }

        #pragma unroll
        for (int kc2 = 0; kc2 < 4; kc2++){
            uint32_t af[4] = {pbh[2*kc2][0], pbh[2*kc2][1],
                              pbh[2*kc2+1][0], pbh[2*kc2+1][1]};
            #pragma unroll
            for (int np = 0; np < 4; np++){
                uint32_t vf[4];
                ldsm_x4t(vf, vb + (uint32_t)((kc2*16 + ((lane >> 3) & 1)*8 + (lane & 7))*144
                                             + (np*2 + (lane >> 4))*16));
                MMA_F16(o[np*2    ], af, vf);
                MMA_F16(o[np*2 + 1], af, vf + 2);
            }
        }

        if (jt + 2 < 16) prefetch(jt + 2);
        CP_COMMIT();
    }

    const float inv0 = 1.0f / l0, inv1 = 1.0f / l1;
    const size_t r0 = (size_t)(b*SEQ + qrow + g);
    #pragma unroll
    for (int nt = 0; nt < 8; nt++){
        const int c = h*DHEAD + nt*8 + 2*t;
        *(uint32_t*)(att + r0      * INNER + c) = ph(o[nt][0]*inv0, o[nt][1]*inv0);
        *(uint32_t*)(att + (r0 + 8) * INNER + c) = ph(o[nt][2]*inv1, o[nt][3]*inv1);
    }
}

// ---------------------------------------------------------------------------
extern "C" void kernel_launch(void* const* d_in, const int* in_sizes, int n_in,
                              void* d_out, int out_size)
{
    const float* x    = (const float*)d_in[0];
    const float* Wqkv = (const float*)d_in[1];
    const float* Wout = (const float*)d_in[2];
    const float* bout = (const float*)d_in[3];
    const float* ln1g = (const float*)d_in[4];
    const float* ln1b = (const float*)d_in[5];
    const float* W1   = (const float*)d_in[6];
    const float* b1   = (const float*)d_in[7];
    const float* W2   = (const float*)d_in[8];
    const float* b2   = (const float*)d_in[9];
    const float* ln2g = (const float*)d_in[10];
    const float* ln2b = (const float*)d_in[11];
    const int*   mnp  = (const int*)d_in[12];
    const int*   mbt  = (const int*)d_in[13];

    float *gx;
    __half *gh, *gqkv, *gatt, *gmlp, *wqkv, *wout, *w1, *w2;
    cudaGetSymbolAddress((void**)&gx,   g_x);
    cudaGetSymbolAddress((void**)&gh,   g_h);
    cudaGetSymbolAddress((void**)&gqkv, g_qkv);
    cudaGetSymbolAddress((void**)&gatt, g_att);
    cudaGetSymbolAddress((void**)&gmlp, g_mlp);
    cudaGetSymbolAddress((void**)&wqkv, g_wqkv);
    cudaGetSymbolAddress((void**)&wout, g_wout);
    cudaGetSymbolAddress((void**)&w1,   g_w1);
    cudaGetSymbolAddress((void**)&w2,   g_w2);

    cudaFuncSetAttribute(hgemm<1>, cudaFuncAttributeMaxDynamicSharedMemorySize, SMTOT);
    cudaFuncSetAttribute(hgemm<2>, cudaFuncAttributeMaxDynamicSharedMemorySize, SMTOT);
    cudaFuncSetAttribute(hgemm<3>, cudaFuncAttributeMaxDynamicSharedMemorySize, SMTOT);
    cudaFuncSetAttribute(flash_kernel, cudaFuncAttributeMaxDynamicSharedMemorySize, FLSM);

    // streaming f32 -> fp16 weight conversion (layout unchanged)
    { int n = DEPTH*DIMM*QKV3/4;  cvt16<<<(n+255)/256, 256>>>(Wqkv, wqkv, n); }
    { int n = DEPTH*INNER*DIMM/4; cvt16<<<(n+255)/256, 256>>>(Wout, wout, n); }
    { int n = DEPTH*DIMM*MLPD/4;  cvt16<<<(n+255)/256, 256>>>(W1,   w1,   n); }
    { int n = DEPTH*MLPD*DIMM/4;  cvt16<<<(n+255)/256, 256>>>(W2,   w2,   n); }

    cudaMemcpyAsync(gx, x, (size_t)TOK * DIMM * sizeof(float),
                    cudaMemcpyDeviceToDevice);

    for (int l = 0; l < DEPTH; l++) {
        ln_kernel<<<TOK, 256>>>(gx, gh, ln1g + l*DIMM, ln1b + l*DIMM);
        hgemm<3><<<dim3(QKV3/128, TOK/128), 256, SMTOT>>>(
            gh, wqkv + (size_t)l*DIMM*QKV3, gqkv, nullptr, nullptr,
            TOK, QKV3, DIMM);
        flash_kernel<<<dim3(SEQ/128, BATCH*HEADS), 256, FLSM>>>(gqkv, gatt, mnp, mbt);
        hgemm<2><<<dim3(DIMM/128, TOK/128), 256, SMTOT>>>(
            gatt, wout + (size_t)l*INNER*DIMM, gx, bout + l*DIMM, gx,
            TOK, DIMM, INNER);
        ln_kernel<<<TOK, 256>>>(gx, gh, ln2g + l*DIMM, ln2b + l*DIMM);
        hgemm<1><<<dim3(MLPD/128, TOK/128), 256, SMTOT>>>(
            gh, w1 + (size_t)l*DIMM*MLPD, gmlp, b1 + l*MLPD, nullptr,
            TOK, MLPD, DIMM);
        hgemm<2><<<dim3(DIMM/128, TOK/128), 256, SMTOT>>>(
            gmlp, w2 + (size_t)l*MLPD*DIMM, gx, b2 + l*DIMM, gx,
            TOK, DIMM, MLPD);
    }

    cudaMemcpyAsync(d_out, gx, (size_t)TOK * DIMM * sizeof(float),
                    cudaMemcpyDeviceToDevice);
}

// round 10
// speedup vs baseline: 2.5959x; 1.0085x over previous
#include <cuda_runtime.h>
#include <cuda_fp16.h>
#include <math.h>
#include <stdint.h>

#define DIMM   1024
#define DEPTH  4
#define HEADS  16
#define DHEAD  64
#define MLPD   4096
#define INNER  1024
#define BATCH  4
#define SEQ    1024
#define TOK    (BATCH*SEQ)
#define QKV3   (3*INNER)

// ---------------- scratch ----------------------------------------------------
__device__ __half g_h  [TOK*DIMM];                 // LN output (fp16)
__device__ __half g_qkv[TOK*QKV3];
__device__ __half g_att[TOK*INNER];
__device__ __half g_mlp[TOK*MLPD];
// fp16 weights, ORIGINAL [K][N] layout (no transpose)
__device__ __half g_wqkv[(size_t)DEPTH*DIMM*QKV3];
__device__ __half g_wout[(size_t)DEPTH*INNER*DIMM];
__device__ __half g_w1  [(size_t)DEPTH*DIMM*MLPD];
__device__ __half g_w2  [(size_t)DEPTH*MLPD*DIMM];

__device__ __forceinline__ uint32_t smem_u32(const void* p){
    return (uint32_t)__cvta_generic_to_shared(p);
}
__device__ __forceinline__ uint32_t ph(float a, float b){
    __half2 h = __floats2half2_rn(a, b);
    return *reinterpret_cast<uint32_t*>(&h);
}
#define CP16(dst, src) asm volatile("cp.async.cg.shared.global [%0], [%1], 16;\n" :: "r"(dst), "l"(src))
#define CP_COMMIT()    asm volatile("cp.async.commit_group;\n" ::: "memory")
#define CP_WAIT1()     asm volatile("cp.async.wait_group 1;\n" ::: "memory")
#define CP_WAIT0()     asm volatile("cp.async.wait_group 0;\n" ::: "memory")

#define MMA_F16(d, a, b) \
  asm volatile("mma.sync.aligned.m16n8k16.row.col.f32.f16.f16.f32 " \
    "{%0,%1,%2,%3},{%4,%5,%6,%7},{%8,%9},{%0,%1,%2,%3};" \
    : "+f"((d)[0]),"+f"((d)[1]),"+f"((d)[2]),"+f"((d)[3]) \
    : "r"((a)[0]),"r"((a)[1]),"r"((a)[2]),"r"((a)[3]),"r"((b)[0]),"r"((b)[1]))

__device__ __forceinline__ void ldsm_x4(uint32_t* r, uint32_t a){
    asm volatile("ldmatrix.sync.aligned.m8n8.x4.shared.b16 {%0,%1,%2,%3}, [%4];"
        : "=r"(r[0]),"=r"(r[1]),"=r"(r[2]),"=r"(r[3]) : "r"(a));
}
__device__ __forceinline__ void ldsm_x4t(uint32_t* r, uint32_t a){
    asm volatile("ldmatrix.sync.aligned.m8n8.x4.trans.shared.b16 {%0,%1,%2,%3}, [%4];"
        : "=r"(r[0]),"=r"(r[1]),"=r"(r[2]),"=r"(r[3]) : "r"(a));
}

// ---------------- streaming f32 -> fp16 convert, 4 float4/thread -------------
// n16 = element count / 16.  Coalesced: thread reads f4[base], [base+256], ...
__global__ void cvt16(const float* __restrict__ in, __half* __restrict__ out, int n16)
{
    const int base = blockIdx.x * 1024 + threadIdx.x;   // in float4 units
    const float4* p4 = (const float4*)in;
    uint2* o2 = (uint2*)out;
    if (blockIdx.x * 1024 + 1024 <= n16 * 4){
        float4 a = p4[base], b = p4[base+256], c = p4[base+512], d = p4[base+768];
        uint2 oa = {ph(a.x,a.y), ph(a.z,a.w)};
        uint2 ob = {ph(b.x,b.y), ph(b.z,b.w)};
        uint2 oc = {ph(c.x,c.y), ph(c.z,c.w)};
        uint2 od = {ph(d.x,d.y), ph(d.z,d.w)};
        o2[base] = oa; o2[base+256] = ob; o2[base+512] = oc; o2[base+768] = od;
    } else {
        #pragma unroll
        for (int j = 0; j < 4; j++){
            const int i = base + j*256;
            if (i < n16 * 4){
                float4 a = p4[i];
                uint2 o = {ph(a.x,a.y), ph(a.z,a.w)};
                o2[i] = o;
            }
        }
    }
}

// ---------------- LayerNorm: warp-per-row (8 rows/block), shfl-only ----------
__global__ void ln_kernel(const float* __restrict__ in, __half* __restrict__ out,
                          const float* __restrict__ gg, const float* __restrict__ bb)
{
    const int warp = threadIdx.x >> 5, lane = threadIdx.x & 31;
    const int row = blockIdx.x * 8 + warp;
    const float4* p = (const float4*)(in + (size_t)row * DIMM);

    float4 v[8];
    float s = 0.f, s2 = 0.f;
    #pragma unroll
    for (int j = 0; j < 8; j++){
        v[j] = p[lane + j*32];
        s  += v[j].x + v[j].y + v[j].z + v[j].w;
        s2 += v[j].x*v[j].x + v[j].y*v[j].y + v[j].z*v[j].z + v[j].w*v[j].w;
    }
    #pragma unroll
    for (int o = 16; o > 0; o >>= 1){
        s  += __shfl_xor_sync(0xffffffffu, s,  o);
        s2 += __shfl_xor_sync(0xffffffffu, s2, o);
    }
    const float mean = s * (1.0f/DIMM);
    const float var  = s2 * (1.0f/DIMM) - mean*mean;
    const float rs   = rsqrtf(var + 1e-5f);

    uint2* orow = (uint2*)(out + (size_t)row * DIMM);
    #pragma unroll
    for (int j = 0; j < 8; j++){
        const float4 gv = ((const float4*)gg)[lane + j*32];
        const float4 bv = ((const float4*)bb)[lane + j*32];
        uint2 o;
        o.x = ph((v[j].x - mean)*rs*gv.x + bv.x, (v[j].y - mean)*rs*gv.y + bv.y);
        o.y = ph((v[j].z - mean)*rs*gv.z + bv.z, (v[j].w - mean)*rs*gv.w + bv.w);
        orow[lane + j*32] = o;
    }
}

// ---------------- FP16 GEMM: B in [K][N], ldmatrix.trans, BK=64, 3-stage -----
// EPI: 1 +bias+GELU -> fp16 ; 2 +bias+residual -> f32 ; 3 plain -> fp16
#define ABYH  18432            // 128*144
#define BBYH  17408            // 64*272
#define STGH  (ABYH+BBYH)      // 35840
#define NSTG  3
#define SMTOT (NSTG*STGH)      // 107520

template<int EPI>
__global__ void __launch_bounds__(256, 2)
hgemm(const __half* __restrict__ A, const __half* __restrict__ B,
      void* __restrict__ Cv, const float* __restrict__ bias,
      const float* __restrict__ R, int M, int Nn, int K)
{
    extern __shared__ char smc[];
    const uint32_t sb = smem_u32(smc);
    const int tid = threadIdx.x, warp = tid >> 5, lane = tid & 31;
    const int g = lane >> 2, t = lane & 3;
    const int wm = (warp >> 2) * 64;
    const int wn = (warp & 3) * 32;
    const int brow = blockIdx.y * 128;
    const int bcol = blockIdx.x * 128;

    float acc[4][4][4];
    #pragma unroll
    for (int i = 0; i < 4; i++)
      #pragma unroll
      for (int j = 0; j < 4; j++)
        { acc[i][j][0]=0.f; acc[i][j][1]=0.f; acc[i][j][2]=0.f; acc[i][j][3]=0.f; }

    auto prefetch = [&](int blk){
        const uint32_t ab = sb + (uint32_t)((blk % NSTG) * STGH);
        const uint32_t bb = ab + ABYH;
        const int kof = blk * 64;
        #pragma unroll
        for (int j = 0; j < 4; j++){
            const int c = tid + j*256;
            const int ar = c >> 3, aq = c & 7;
            CP16(ab + (uint32_t)(ar*144 + aq*16), A + (size_t)(brow+ar)*K + kof + aq*8);
            const int br2 = c >> 4, bq = c & 15;
            CP16(bb + (uint32_t)(br2*272 + bq*16), B + (size_t)(kof+br2)*Nn + bcol + bq*8);
        }
    };

    prefetch(0); CP_COMMIT();
    prefetch(1); CP_COMMIT();

    const uint32_t aoff = (uint32_t)((wm + (lane & 15))*144 + (lane >> 4)*16);
    const uint32_t boffl = (uint32_t)((lane & 15)*272 + (wn + ((lane >> 4) & 1)*8)*2) + ABYH;

    const int nk = K >> 6;
    for (int i = 0; i < nk; i++){
        CP_WAIT1();
        __syncthreads();
        const uint32_t stg = sb + (uint32_t)((i % NSTG) * STGH);
        #pragma unroll
        for (int s = 0; s < 4; s++){
            uint32_t af[4][4], bq2[2][4];
            #pragma unroll
            for (int mt = 0; mt < 4; mt++)
                ldsm_x4(af[mt], stg + aoff + (uint32_t)(mt*2304 + s*32));
            #pragma unroll
            for (int np = 0; np < 2; np++)
                ldsm_x4t(bq2[np], stg + boffl + (uint32_t)(s*4352 + np*32));
            #pragma unroll
            for (int mt = 0; mt < 4; mt++)
              #pragma unroll
              for (int nt = 0; nt < 4; nt++)
                MMA_F16(acc[mt][nt], af[mt], &bq2[nt >> 1][(nt & 1)*2]);
        }
        if (i + 2 < nk) prefetch(i + 2);
        CP_COMMIT();
    }

    #pragma unroll
    for (int mt = 0; mt < 4; mt++){
        const int r0 = brow + wm + mt*16 + g;
        #pragma unroll
        for (int nt = 0; nt < 4; nt++){
            const int c = bcol + wn + nt*8 + 2*t;
            float v[4] = {acc[mt][nt][0], acc[mt][nt][1], acc[mt][nt][2], acc[mt][nt][3]};
            if (EPI == 1 || EPI == 2){
                const float b0 = bias[c], b1 = bias[c+1];
                v[0]+=b0; v[1]+=b1; v[2]+=b0; v[3]+=b1;
            }
            if (EPI == 1){
                #pragma unroll
                for (int q = 0; q < 4; q++)
                    v[q] = 0.5f * v[q] * (1.0f + erff(v[q] * 0.70710678118654752f));
            }
            if (EPI == 2){
                float* Cf = (float*)Cv;
                const float2 r0v = *(const float2*)(R + (size_t)r0*Nn + c);
                const float2 r1v = *(const float2*)(R + (size_t)(r0+8)*Nn + c);
                float2 o0 = {v[0]+r0v.x, v[1]+r0v.y}, o1 = {v[2]+r1v.x, v[3]+r1v.y};
                *(float2*)(Cf + (size_t)r0    *Nn + c) = o0;
                *(float2*)(Cf + (size_t)(r0+8)*Nn + c) = o1;
            } else {
                __half* Ch = (__half*)Cv;
                *(uint32_t*)(Ch + (size_t)r0    *Nn + c) = ph(v[0], v[1]);
                *(uint32_t*)(Ch + (size_t)(r0+8)*Nn + c) = ph(v[2], v[3]);
            }
        }
    }
}

// ---------------- Fused fp16 flash attention, double-buffered K/V ------------
#define FKV   18432
#define FLSM  (3*FKV + 4096)

__global__ void __launch_bounds__(256, 2)
flash_kernel(const __half* __restrict__ qkv, __half* __restrict__ att,
             const int* __restrict__ mnp, const int* __restrict__ mbt)
{
    extern __shared__ char fsm[];
    const uint32_t base = smem_u32(fsm);
    float* cmask = (float*)(fsm + 3*FKV);

    const int tid = threadIdx.x, warp = tid >> 5, lane = tid & 31;
    const int g = lane >> 2, t = lane & 3;
    const int bh = blockIdx.y, b = bh >> 4, h = bh & 15;
    const int i0 = blockIdx.x * 128;

    const __half* qb    = qkv + (size_t)(b*SEQ + i0) * QKV3 + h*DHEAD;
    const __half* kbase = qkv + (size_t)(b*SEQ) * QKV3 + INNER   + h*DHEAD;
    const __half* vbase = qkv + (size_t)(b*SEQ) * QKV3 + 2*INNER + h*DHEAD;

    {
        const int j = tid * 4;
        const int4 a = *(const int4*)(mnp + b*SEQ + j);
        const int4 c = *(const int4*)(mbt + b*SEQ + j);
        cmask[j+0] = (a.x != 0 && c.x != 1) ? 1.f : 0.f;
        cmask[j+1] = (a.y != 0 && c.y != 1) ? 1.f : 0.f;
        cmask[j+2] = (a.z != 0 && c.z != 1) ? 1.f : 0.f;
        cmask[j+3] = (a.w != 0 && c.w != 1) ? 1.f : 0.f;
    }

    #pragma unroll
    for (int it = 0; it < 4; it++){
        const int idx = tid + it*256;
        const int r = idx >> 3, q = idx & 7;
        const uint32_t dst = (r < 64) ? (base + (uint32_t)(r*144 + q*16))
                                      : (base + 9216 + (uint32_t)((r-64)*144 + q*16));
        CP16(dst, qb + (size_t)r*QKV3 + q*8);
    }
    CP_COMMIT(); CP_WAIT0();
    __syncthreads();

    uint32_t qa[4][4];
    {
        const uint32_t qbase = (warp < 4) ? base : (base + 9216);
        const int row0 = (warp & 3) * 16;
        #pragma unroll
        for (int kc = 0; kc < 4; kc++)
            ldsm_x4(qa[kc], qbase + (uint32_t)((row0 + (lane & 15))*144
                                               + (lane >> 4)*16 + kc*32));
    }
    __syncthreads();

    auto prefetch = [&](int jt){
        const uint32_t kb = base + (uint32_t)((jt % 3) * FKV);
        const uint32_t vb = kb + 9216;
        #pragma unroll
        for (int it = 0; it < 2; it++){
            const int idx = tid + it*256;
            const int r = idx >> 3, q = idx & 7;
            const size_t gr = (size_t)(jt*64 + r) * QKV3 + q*8;
            CP16(kb + (uint32_t)(r*144 + q*16), kbase + gr);
            CP16(vb + (uint32_t)(r*144 + q*16), vbase + gr);
        }
    };
    prefetch(0); CP_COMMIT();
    prefetch(1); CP_COMMIT();

    const int qrow = i0 + warp*16;
    const bool rm0 = (mnp[b*SEQ + qrow + g    ] == 0);
    const bool rm1 = (mnp[b*SEQ + qrow + g + 8] == 0);

    float m0 = -1e30f, m1 = -1e30f, l0 = 0.f, l1 = 0.f;
    float o[8][4];
    #pragma unroll
    for (int nt = 0; nt < 8; nt++){ o[nt][0]=0.f; o[nt][1]=0.f; o[nt][2]=0.f; o[nt][3]=0.f; }

    for (int jt = 0; jt < 16; jt++){
        CP_WAIT1();
        __syncthreads();
        const uint32_t kb = base + (uint32_t)((jt % 3) * FKV);
        const uint32_t vb = kb + 9216;

        float s[8][4];
        #pragma unroll
        for (int nc = 0; nc < 8; nc++){ s[nc][0]=0.f; s[nc][1]=0.f; s[nc][2]=0.f; s[nc][3]=0.f; }
        #pragma unroll
        for (int kc = 0; kc < 4; kc++){
            #pragma unroll
            for (int np = 0; np < 4; np++){
                uint32_t kf[4];
                ldsm_x4(kf, kb + (uint32_t)((np*16 + (lane >> 4)*8 + (lane & 7))*144
                                            + ((lane >> 3) & 1)*16 + kc*32));
                MMA_F16(s[np*2    ], qa[kc], kf);
                MMA_F16(s[np*2 + 1], qa[kc], kf + 2);
            }
        }

        float mx0 = -1e30f, mx1 = -1e30f;
        #pragma unroll
        for (int nc = 0; nc < 8; nc++){
            const int j = jt*64 + nc*8 + 2*t;
            const float c0v = cmask[j], c1v = cmask[j+1];
            s[nc][0] = (rm0 || c0v == 0.f) ? -1000.f : s[nc][0]*0.125f;
            s[nc][1] = (rm0 || c1v == 0.f) ? -1000.f : s[nc][1]*0.125f;
            s[nc][2] = (rm1 || c0v == 0.f) ? -1000.f : s[nc][2]*0.125f;
            s[nc][3] = (rm1 || c1v == 0.f) ? -1000.f : s[nc][3]*0.125f;
            mx0 = fmaxf(mx0, fmaxf(s[nc][0], s[nc][1]));
            mx1 = fmaxf(mx1, fmaxf(s[nc][2], s[nc][3]));
        }
        mx0 = fmaxf(mx0, __shfl_xor_sync(0xffffffffu, mx0, 1));
        mx0 = fmaxf(mx0, __shfl_xor_sync(0xffffffffu, mx0, 2));
        mx1 = fmaxf(mx1, __shfl_xor_sync(0xffffffffu, mx1, 1));
        mx1 = fmaxf(mx1, __shfl_xor_sync(0xffffffffu, mx1, 2));

        const float nm0 = fmaxf(m0, mx0), nm1 = fmaxf(m1, mx1);
        const float a0 = __expf(m0 - nm0), a1 = __expf(m1 - nm1);

        float r0s = 0.f, r1s = 0.f;
        uint32_t pbh[8][2];
        #pragma unroll
        for (int nc = 0; nc < 8; nc++){
            const float e0 = __expf(s[nc][0] - nm0);
            const float e1 = __expf(s[nc][1] - nm0);
            const float e2 = __expf(s[nc][2] - nm1);
            const float e3 = __expf(s[nc][3] - nm1);
            r0s += e0 + e1; r1s += e2 + e3;
            pbh[nc][0] = ph(e0, e1);
            pbh[nc][1] = ph(e2, e3);
        }
        r0s += __shfl_xor_sync(0xffffffffu, r0s, 1);
        r0s += __shfl_xor_sync(0xffffffffu, r0s, 2);
        r1s += __shfl_xor_sync(0xffffffffu, r1s, 1);
        r1s += __shfl_xor_sync(0xffffffffu, r1s, 2);

        l0 = l0*a0 + r0s; l1 = l1*a1 + r1s;
        m0 = nm0; m1 = nm1;

        #pragma unroll
        for (int nt = 0; nt < 8; nt++){
            o[nt][0] *= a0; o[nt][1] *= a0;
            o[nt][2] *= a1; o[nt][3] *= a1;
        }

        #pragma unroll
        for (int kc2 = 0; kc2 < 4; kc2++){
            uint32_t af[4] = {pbh[2*kc2][0], pbh[2*kc2][1],
                              pbh[2*kc2+1][0], pbh[2*kc2+1][1]};
            #pragma unroll
            for (int np = 0; np < 4; np++){
                uint32_t vf[4];
                ldsm_x4t(vf, vb + (uint32_t)((kc2*16 + ((lane >> 3) & 1)*8 + (lane & 7))*144
                                             + (np*2 + (lane >> 4))*16));
                MMA_F16(o[np*2    ], af, vf);
                MMA_F16(o[np*2 + 1], af, vf + 2);
            }
        }

        if (jt + 2 < 16) prefetch(jt + 2);
        CP_COMMIT();
    }

    const float inv0 = 1.0f / l0, inv1 = 1.0f / l1;
    const size_t r0 = (size_t)(b*SEQ + qrow + g);
    #pragma unroll
    for (int nt = 0; nt < 8; nt++){
        const int c = h*DHEAD + nt*8 + 2*t;
        *(uint32_t*)(att + r0      * INNER + c) = ph(o[nt][0]*inv0, o[nt][1]*inv0);
        *(uint32_t*)(att + (r0 + 8) * INNER + c) = ph(o[nt][2]*inv1, o[nt][3]*inv1);
    }
}

// ---------------------------------------------------------------------------
extern "C" void kernel_launch(void* const* d_in, const int* in_sizes, int n_in,
                              void* d_out, int out_size)
{
    const float* x    = (const float*)d_in[0];
    const float* Wqkv = (const float*)d_in[1];
    const float* Wout = (const float*)d_in[2];
    const float* bout = (const float*)d_in[3];
    const float* ln1g = (const float*)d_in[4];
    const float* ln1b = (const float*)d_in[5];
    const float* W1   = (const float*)d_in[6];
    const float* b1   = (const float*)d_in[7];
    const float* W2   = (const float*)d_in[8];
    const float* b2   = (const float*)d_in[9];
    const float* ln2g = (const float*)d_in[10];
    const float* ln2b = (const float*)d_in[11];
    const int*   mnp  = (const int*)d_in[12];
    const int*   mbt  = (const int*)d_in[13];

    float* gx = (float*)d_out;   // residual stream lives in the output buffer
    __half *gh, *gqkv, *gatt, *gmlp, *wqkv, *wout, *w1, *w2;
    cudaGetSymbolAddress((void**)&gh,   g_h);
    cudaGetSymbolAddress((void**)&gqkv, g_qkv);
    cudaGetSymbolAddress((void**)&gatt, g_att);
    cudaGetSymbolAddress((void**)&gmlp, g_mlp);
    cudaGetSymbolAddress((void**)&wqkv, g_wqkv);
    cudaGetSymbolAddress((void**)&wout, g_wout);
    cudaGetSymbolAddress((void**)&w1,   g_w1);
    cudaGetSymbolAddress((void**)&w2,   g_w2);

    cudaFuncSetAttribute(hgemm<1>, cudaFuncAttributeMaxDynamicSharedMemorySize, SMTOT);
    cudaFuncSetAttribute(hgemm<2>, cudaFuncAttributeMaxDynamicSharedMemorySize, SMTOT);
    cudaFuncSetAttribute(hgemm<3>, cudaFuncAttributeMaxDynamicSharedMemorySize, SMTOT);
    cudaFuncSetAttribute(flash_kernel, cudaFuncAttributeMaxDynamicSharedMemorySize, FLSM);

    // streaming f32 -> fp16 weight conversion (layout unchanged), 16 floats/thr
    { int n = DEPTH*DIMM*QKV3/16;  cvt16<<<(n+255)/256, 256>>>(Wqkv, wqkv, n); }
    { int n = DEPTH*INNER*DIMM/16; cvt16<<<(n+255)/256, 256>>>(Wout, wout, n); }
    { int n = DEPTH*DIMM*MLPD/16;  cvt16<<<(n+255)/256, 256>>>(W1,   w1,   n); }
    { int n = DEPTH*MLPD*DIMM/16;  cvt16<<<(n+255)/256, 256>>>(W2,   w2,   n); }

    cudaMemcpyAsync(gx, x, (size_t)TOK * DIMM * sizeof(float),
                    cudaMemcpyDeviceToDevice);

    for (int l = 0; l < DEPTH; l++) {
        ln_kernel<<<TOK/8, 256>>>(gx, gh, ln1g + l*DIMM, ln1b + l*DIMM);
        hgemm<3><<<dim3(QKV3/128, TOK/128), 256, SMTOT>>>(
            gh, wqkv + (size_t)l*DIMM*QKV3, gqkv, nullptr, nullptr,
            TOK, QKV3, DIMM);
        flash_kernel<<<dim3(SEQ/128, BATCH*HEADS), 256, FLSM>>>(gqkv, gatt, mnp, mbt);
        hgemm<2><<<dim3(DIMM/128, TOK/128), 256, SMTOT>>>(
            gatt, wout + (size_t)l*INNER*DIMM, gx, bout + l*DIMM, gx,
            TOK, DIMM, INNER);
        ln_kernel<<<TOK/8, 256>>>(gx, gh, ln2g + l*DIMM, ln2b + l*DIMM);
        hgemm<1><<<dim3(MLPD/128, TOK/128), 256, SMTOT>>>(
            gh, w1 + (size_t)l*DIMM*MLPD, gmlp, b1 + l*MLPD, nullptr,
            TOK, MLPD, DIMM);
        hgemm<2><<<dim3(DIMM/128, TOK/128), 256, SMTOT>>>(
            gmlp, w2 + (size_t)l*MLPD*DIMM, gx, b2 + l*DIMM, gx,
            TOK, DIMM, MLPD);
    }
    // residual stream IS d_out — no final copy needed
}